// round 10
// baseline (speedup 1.0000x reference)
#include <cuda_runtime.h>
#include <cuda_bf16.h>
#include <cstdint>

// WindowAttention fused, R9: all gemms on mma.sync bf16 split hi/lo (3 products).
// Pre-kernels build split-bf16 weight images + combined bias/mask table once per
// launch; main kernel stages weights via cp.async flat copies and fuses
// S-epilogue + softmax + P-store in registers. 512 threads, one CTA/window.

#define NTOK  49
#define DIMC  128
#define NHEAD 4
#define HDIM  32
#define NWIN  64
#define NTHREADS 512

#define APITCH 272    // bytes/row, 128-col bf16 tiles (17*16B, ldmatrix conflict-free)
#define VPITCH 144    // bytes/row, 64-col bf16 tiles (9*16B)

// smem byte layout
#define SM_XHI 0
#define SM_XLO 17408
#define SM_WHI 34816
#define SM_WLO 69632
#define SM_QHI 104448
#define SM_QLO 121856
#define SM_KHI 139264
#define SM_KLO 156672
#define SM_VHI 174080
#define SM_VLO 192512
#define SM_RED 210944              // softmax partials: 4*64*4 floats = 4096 B
#define SMEM_TOTAL 215040
#define SM_PHI SM_QHI              // P probs 196*144*2 = 56448, overlays Q/K
#define SM_PLO (SM_PHI + 196*VPITCH)

#define WCHUNK_BYTES 69632         // hi(34816)+lo(34816) contiguous
#define WCHUNK_V16   4352          // 16B transfers per chunk

// device-global scratch (allowed; no allocation)
__device__ __align__(16) unsigned char g_wimg[4 * WCHUNK_BYTES];  // q,k,v,proj images
__device__ float g_comb[NWIN * NHEAD * NTOK * NTOK];              // bias+mask, 2.46MB

__device__ __forceinline__ uint32_t smem_u32(const void* p) {
    uint32_t a;
    asm("{ .reg .u64 t; cvta.to.shared.u64 t, %1; cvt.u32.u64 %0, t; }" : "=r"(a) : "l"(p));
    return a;
}
__device__ __forceinline__ void ldsm4(uint32_t r[4], uint32_t a) {
    asm volatile("ldmatrix.sync.aligned.m8n8.x4.shared.b16 {%0,%1,%2,%3}, [%4];"
                 : "=r"(r[0]), "=r"(r[1]), "=r"(r[2]), "=r"(r[3]) : "r"(a));
}
__device__ __forceinline__ void mma16816(float c[4], const uint32_t a[4], uint32_t b0, uint32_t b1) {
    asm volatile("mma.sync.aligned.m16n8k16.row.col.f32.bf16.bf16.f32 "
                 "{%0,%1,%2,%3}, {%4,%5,%6,%7}, {%8,%9}, {%0,%1,%2,%3};"
                 : "+f"(c[0]), "+f"(c[1]), "+f"(c[2]), "+f"(c[3])
                 : "r"(a[0]), "r"(a[1]), "r"(a[2]), "r"(a[3]), "r"(b0), "r"(b1));
}
// pack (v0,v1) -> bf16x2 hi + bf16x2 residual-lo, two 32-bit stores
__device__ __forceinline__ void split_store2(float v0, float v1, char* hi, char* lo, uint32_t off) {
    uint32_t hp;
    asm("cvt.rn.bf16x2.f32 %0, %1, %2;" : "=r"(hp) : "f"(v1), "f"(v0));
    float hf0 = __uint_as_float(hp << 16);
    float hf1 = __uint_as_float(hp & 0xFFFF0000u);
    uint32_t lp;
    asm("cvt.rn.bf16x2.f32 %0, %1, %2;" : "=r"(lp) : "f"(v1 - hf1), "f"(v0 - hf0));
    *(uint32_t*)(hi + off) = hp;
    *(uint32_t*)(lo + off) = lp;
}
__device__ __forceinline__ void split_store(float v, char* hi, char* lo, uint32_t off) {
    __nv_bfloat16 h = __float2bfloat16(v);
    *(__nv_bfloat16*)(hi + off) = h;
    *(__nv_bfloat16*)(lo + off) = __float2bfloat16(v - __bfloat162float(h));
}

__device__ __forceinline__ void copy_w_chunk(uint32_t sb, const unsigned char* src, int t) {
    #pragma unroll
    for (int i = 0; i < 9; ++i) {
        int idx = t + i * NTHREADS;
        if (idx < WCHUNK_V16)
            asm volatile("cp.async.cg.shared.global [%0], [%1], 16;"
                         :: "r"(sb + SM_WHI + idx * 16), "l"(src + idx * 16));
    }
    asm volatile("cp.async.commit_group;");
}
#define CP_WAIT0() asm volatile("cp.async.wait_group 0;" ::: "memory")

// C[64x128] = A[64x128] * B[128x128]^T, split-bf16 3-product, 16 warps m32n16.
__device__ __forceinline__ void hmma_gemm_128(uint32_t aHiB, uint32_t aLoB,
                                              uint32_t bHiB, uint32_t bLoB,
                                              int wid, int lane, float acc[2][2][4]) {
    const int m0 = (wid >> 3) * 32, n0 = (wid & 7) * 16;
    const uint32_t aoff = (uint32_t)((m0 + (lane & 15)) * APITCH + (lane & 16));
    const uint32_t boff = (uint32_t)((n0 + (lane & 7)) * APITCH + ((lane >> 3) << 4));
    const uint32_t aHi = aHiB + aoff, aLo = aLoB + aoff;
    const uint32_t bHi = bHiB + boff, bLo = bLoB + boff;
    #pragma unroll
    for (int kk = 0; kk < 4; ++kk) {
        const int k0 = kk * 32;
        uint32_t bh[2][4], bl[2][4];
        #pragma unroll
        for (int ni = 0; ni < 2; ++ni) {
            ldsm4(bh[ni], bHi + ni * 8 * APITCH + k0 * 2);
            ldsm4(bl[ni], bLo + ni * 8 * APITCH + k0 * 2);
        }
        #pragma unroll
        for (int half = 0; half < 2; ++half) {
            const int k16 = k0 + half * 16;
            uint32_t ah[2][4], al[2][4];
            ldsm4(ah[0], aHi + k16 * 2);
            ldsm4(ah[1], aHi + 16 * APITCH + k16 * 2);
            ldsm4(al[0], aLo + k16 * 2);
            ldsm4(al[1], aLo + 16 * APITCH + k16 * 2);
            #pragma unroll
            for (int mi = 0; mi < 2; ++mi)
                #pragma unroll
                for (int ni = 0; ni < 2; ++ni) {
                    uint32_t b0 = bh[ni][2 * half], b1 = bh[ni][2 * half + 1];
                    mma16816(acc[mi][ni], ah[mi], b0, b1);
                    mma16816(acc[mi][ni], al[mi], b0, b1);
                    mma16816(acc[mi][ni], ah[mi], bl[ni][2 * half], bl[ni][2 * half + 1]);
                }
        }
    }
}

// ---------------- pre-kernels ----------------
__global__ void prep_weights(const float* __restrict__ qkv_w, const float* __restrict__ proj_w)
{
    int idx = blockIdx.x * blockDim.x + threadIdx.x;   // 32768 = 4 chunks * 128 rows * 64 pairs
    if (idx >= 4 * 128 * 64) return;
    int c = idx >> 13, n = (idx >> 6) & 127, k = (idx & 63) * 2;
    const float* src = (c < 3) ? (qkv_w + (size_t)(c * 128 + n) * DIMC + k)
                               : (proj_w + (size_t)n * DIMC + k);
    float v0 = src[0], v1 = src[1];
    uint32_t hp;
    asm("cvt.rn.bf16x2.f32 %0, %1, %2;" : "=r"(hp) : "f"(v1), "f"(v0));
    float hf0 = __uint_as_float(hp << 16);
    float hf1 = __uint_as_float(hp & 0xFFFF0000u);
    uint32_t lp;
    asm("cvt.rn.bf16x2.f32 %0, %1, %2;" : "=r"(lp) : "f"(v1 - hf1), "f"(v0 - hf0));
    uint32_t off = (uint32_t)(n * APITCH + k * 2);
    *(uint32_t*)(g_wimg + c * WCHUNK_BYTES + off)         = hp;
    *(uint32_t*)(g_wimg + c * WCHUNK_BYTES + 34816 + off) = lp;
}

__global__ void prep_comb(const float* __restrict__ attn_mask,
                          const float* __restrict__ rpb_table,
                          const int*   __restrict__ rpb_index)
{
    int idx = blockIdx.x * blockDim.x + threadIdx.x;
    if (idx >= NWIN * NHEAD * NTOK * NTOK) return;
    int win = idx / (NHEAD * NTOK * NTOK);
    int rem = idx - win * (NHEAD * NTOK * NTOK);
    int h  = rem / (NTOK * NTOK);
    int ij = rem - h * (NTOK * NTOK);
    g_comb[idx] = rpb_table[rpb_index[ij] * NHEAD + h] + attn_mask[win * NTOK * NTOK + ij];
}

// ---------------- main kernel ----------------
__global__ void __launch_bounds__(NTHREADS, 1)
swin_attn_kernel(const float* __restrict__ x,
                 const float* __restrict__ qkv_b,
                 const float* __restrict__ proj_b,
                 float*       __restrict__ out)
{
    extern __shared__ char smem[];
    const uint32_t sb = smem_u32(smem);
    char* xhi = smem + SM_XHI;  char* xlo = smem + SM_XLO;
    char* qhi = smem + SM_QHI;  char* qlo = smem + SM_QLO;
    char* khi = smem + SM_KHI;  char* klo = smem + SM_KLO;
    char* phi = smem + SM_PHI;  char* plo = smem + SM_PLO;
    char* vhi = smem + SM_VHI;  char* vlo = smem + SM_VLO;
    float* red = (float*)(smem + SM_RED);

    const int t = threadIdx.x, wid = t >> 5, lane = t & 31;
    const int bnw = blockIdx.x, win = bnw & (NWIN - 1);
    const int tr = lane >> 2, tc = (lane & 3) * 2;

    // issue chunk-0 weight copy first (overlaps X conversion below)
    copy_w_chunk(sb, g_wimg, t);

    // zero V^T token-pad cols 48..63
    for (int idx = t; idx < 128 * 8; idx += NTHREADS) {
        int r = idx >> 3, w4 = idx & 7;
        *(uint32_t*)(vhi + r * VPITCH + 96 + w4 * 4) = 0u;
        *(uint32_t*)(vlo + r * VPITCH + 96 + w4 * 4) = 0u;
    }
    // stage X (49x128) split bf16
    {
        const float4* xg = (const float4*)(x + (size_t)bnw * NTOK * DIMC);
        for (int idx = t; idx < NTOK * DIMC / 4; idx += NTHREADS) {
            int r = idx >> 5, c = (idx & 31) << 2;
            float4 v = xg[idx];
            uint32_t o = (uint32_t)(r * APITCH + c * 2);
            split_store2(v.x, v.y, xhi, xlo, o);
            split_store2(v.z, v.w, xhi, xlo, o + 4);
        }
    }
    CP_WAIT0();
    __syncthreads();

    // ---- QKV chunks 0=q,1=k,2=v ----
    for (int chunk = 0; chunk < 3; ++chunk) {
        float acc[2][2][4];
        #pragma unroll
        for (int mi = 0; mi < 2; ++mi)
            #pragma unroll
            for (int ni = 0; ni < 2; ++ni)
                #pragma unroll
                for (int q = 0; q < 4; ++q) acc[mi][ni][q] = 0.f;

        hmma_gemm_128(sb + SM_XHI, sb + SM_XLO, sb + SM_WHI, sb + SM_WLO, wid, lane, acc);

        const int m0 = (wid >> 3) * 32, n0 = (wid & 7) * 16;
        #pragma unroll
        for (int mi = 0; mi < 2; ++mi)
            #pragma unroll
            for (int ni = 0; ni < 2; ++ni) {
                int col = n0 + ni * 8 + tc;
                float b0 = qkv_b[chunk * 128 + col];
                float b1 = qkv_b[chunk * 128 + col + 1];
                #pragma unroll
                for (int h2 = 0; h2 < 2; ++h2) {
                    int m = m0 + mi * 16 + tr + h2 * 8;
                    if (m < NTOK) {
                        float v0 = acc[mi][ni][2 * h2] + b0;
                        float v1 = acc[mi][ni][2 * h2 + 1] + b1;
                        if (chunk == 0)
                            split_store2(v0, v1, qhi, qlo, (uint32_t)(m * APITCH + col * 2));
                        else if (chunk == 1)
                            split_store2(v0, v1, khi, klo, (uint32_t)(m * APITCH + col * 2));
                        else {   // V^T: row = dim, col = token
                            split_store(v0, vhi, vlo, (uint32_t)(col * VPITCH + m * 2));
                            split_store(v1, vhi, vlo, (uint32_t)((col + 1) * VPITCH + m * 2));
                        }
                    }
                }
            }
        __syncthreads();                                    // W region free
        copy_w_chunk(sb, g_wimg + (chunk + 1) * WCHUNK_BYTES, t);   // chunk2 -> proj image
        if (chunk < 2) { CP_WAIT0(); __syncthreads(); }
        // proj copy left in flight: overlaps S/softmax/AV
    }

    // ---- S = Q K^T per head (K=32) + fused softmax + P store ----
    {
        const int h = wid >> 2, sub = wid & 3;
        const int ms = (sub >> 1) * 32, ns = (sub & 1) * 32;
        const uint32_t aoff = (uint32_t)((ms + (lane & 15)) * APITCH + (lane & 16) + h * 64);
        const uint32_t boff = (uint32_t)((ns + (lane & 7)) * APITCH + ((lane >> 3) << 4) + h * 64);
        const uint32_t aHi = sb + SM_QHI + aoff, aLo = sb + SM_QLO + aoff;
        const uint32_t bHi = sb + SM_KHI + boff, bLo = sb + SM_KLO + boff;

        float accS[2][4][4];
        #pragma unroll
        for (int mi = 0; mi < 2; ++mi)
            #pragma unroll
            for (int ni = 0; ni < 4; ++ni)
                #pragma unroll
                for (int q = 0; q < 4; ++q) accS[mi][ni][q] = 0.f;

        uint32_t bh[4][4], bl[4][4];
        #pragma unroll
        for (int ni = 0; ni < 4; ++ni) {
            ldsm4(bh[ni], bHi + ni * 8 * APITCH);
            ldsm4(bl[ni], bLo + ni * 8 * APITCH);
        }
        #pragma unroll
        for (int half = 0; half < 2; ++half) {
            uint32_t ah[2][4], al[2][4];
            ldsm4(ah[0], aHi + half * 32);
            ldsm4(ah[1], aHi + 16 * APITCH + half * 32);
            ldsm4(al[0], aLo + half * 32);
            ldsm4(al[1], aLo + 16 * APITCH + half * 32);
            #pragma unroll
            for (int mi = 0; mi < 2; ++mi)
                #pragma unroll
                for (int ni = 0; ni < 4; ++ni) {
                    uint32_t b0 = bh[ni][2 * half], b1 = bh[ni][2 * half + 1];
                    mma16816(accS[mi][ni], ah[mi], b0, b1);
                    mma16816(accS[mi][ni], al[mi], b0, b1);
                    mma16816(accS[mi][ni], ah[mi], bl[ni][2 * half], bl[ni][2 * half + 1]);
                }
        }

        // fused epilogue: scale + comb, row max/sum (quad shuffles), partials to smem
        const float scale = 0.17677669529663687f;
        const float* combp = g_comb + win * (NHEAD * NTOK * NTOK) + h * (NTOK * NTOK);
        float e[4][8], ml[4];
        #pragma unroll
        for (int rs = 0; rs < 4; ++rs) {
            int i = ms + tr + (rs >> 1) * 16 + (rs & 1) * 8;
            bool irow = (i < NTOK);
            float vr[8];
            #pragma unroll
            for (int cs = 0; cs < 8; ++cs) {
                int j = ns + tc + ((cs >> 1) << 3) + (cs & 1);
                float a = accS[rs >> 1][cs >> 1][((rs & 1) << 1) | (cs & 1)];
                vr[cs] = (irow && j < NTOK) ? fmaf(a, scale, combp[i * NTOK + j]) : -1e30f;
            }
            float m = vr[0];
            #pragma unroll
            for (int cs = 1; cs < 8; ++cs) m = fmaxf(m, vr[cs]);
            m = fmaxf(m, __shfl_xor_sync(~0u, m, 1));
            m = fmaxf(m, __shfl_xor_sync(~0u, m, 2));
            float s = 0.f;
            #pragma unroll
            for (int cs = 0; cs < 8; ++cs) { e[rs][cs] = __expf(vr[cs] - m); s += e[rs][cs]; }
            s += __shfl_xor_sync(~0u, s, 1);
            s += __shfl_xor_sync(~0u, s, 2);
            ml[rs] = m;
            if ((lane & 3) == 0) {
                int rb = (h * 64 + i) * 4 + (ns >> 5) * 2;
                red[rb] = m; red[rb + 1] = s;
            }
        }
        __syncthreads();

        // combine halves, normalize, split-store P (pads get exact zeros)
        #pragma unroll
        for (int rs = 0; rs < 4; ++rs) {
            int i = ms + tr + (rs >> 1) * 16 + (rs & 1) * 8;
            if (i >= NTOK) continue;
            int rb = (h * 64 + i) * 4;
            float m0 = red[rb], s0 = red[rb + 1], m1 = red[rb + 2], s1 = red[rb + 3];
            float M = fmaxf(m0, m1);
            float S = s0 * __expf(m0 - M) + s1 * __expf(m1 - M);
            float f = __expf(ml[rs] - M) / S;
            uint32_t prow = (uint32_t)((h * NTOK + i) * VPITCH);
            #pragma unroll
            for (int cp2 = 0; cp2 < 4; ++cp2) {
                int j = ns + tc + cp2 * 8;
                split_store2(e[rs][2 * cp2] * f, e[rs][2 * cp2 + 1] * f, phi, plo,
                             prow + (uint32_t)(j * 2));
            }
        }
    }
    __syncthreads();

    // ---- AV gemm (P[196x64] x V^T per head) -> y into X tiles ----
    {
        const int h = wid >> 2, sub = wid & 3;
        const int ms = (sub >> 1) * 32, ns2 = (sub & 1) * 16;
        const uint32_t aoff = (uint32_t)((h * NTOK + ms + (lane & 15)) * VPITCH + (lane & 16));
        const uint32_t boff = (uint32_t)((h * HDIM + ns2 + (lane & 7)) * VPITCH + ((lane >> 3) << 4));
        const uint32_t aHi = sb + SM_PHI + aoff, aLo = sb + SM_PLO + aoff;
        const uint32_t bHi = sb + SM_VHI + boff, bLo = sb + SM_VLO + boff;

        float accv[2][2][4];
        #pragma unroll
        for (int mi = 0; mi < 2; ++mi)
            #pragma unroll
            for (int ni = 0; ni < 2; ++ni)
                #pragma unroll
                for (int q = 0; q < 4; ++q) accv[mi][ni][q] = 0.f;

        #pragma unroll
        for (int kk = 0; kk < 2; ++kk) {
            const int k0 = kk * 32;
            uint32_t bh[2][4], bl[2][4];
            #pragma unroll
            for (int ni = 0; ni < 2; ++ni) {
                ldsm4(bh[ni], bHi + ni * 8 * VPITCH + k0 * 2);
                ldsm4(bl[ni], bLo + ni * 8 * VPITCH + k0 * 2);
            }
            #pragma unroll
            for (int half = 0; half < 2; ++half) {
                const int k16 = k0 + half * 16;
                uint32_t ah[2][4], al[2][4];
                ldsm4(ah[0], aHi + k16 * 2);
                ldsm4(ah[1], aHi + 16 * VPITCH + k16 * 2);
                ldsm4(al[0], aLo + k16 * 2);
                ldsm4(al[1], aLo + 16 * VPITCH + k16 * 2);
                #pragma unroll
                for (int mi = 0; mi < 2; ++mi)
                    #pragma unroll
                    for (int ni = 0; ni < 2; ++ni) {
                        uint32_t b0 = bh[ni][2 * half], b1 = bh[ni][2 * half + 1];
                        mma16816(accv[mi][ni], ah[mi], b0, b1);
                        mma16816(accv[mi][ni], al[mi], b0, b1);
                        mma16816(accv[mi][ni], ah[mi], bl[ni][2 * half], bl[ni][2 * half + 1]);
                    }
            }
        }
        #pragma unroll
        for (int mi = 0; mi < 2; ++mi)
            #pragma unroll
            for (int ni = 0; ni < 2; ++ni)
                #pragma unroll
                for (int h2 = 0; h2 < 2; ++h2) {
                    int i = ms + mi * 16 + tr + h2 * 8;
                    if (i < NTOK) {
                        int col = h * HDIM + ns2 + ni * 8 + tc;
                        split_store2(accv[mi][ni][2 * h2], accv[mi][ni][2 * h2 + 1],
                                     xhi, xlo, (uint32_t)(i * APITCH + col * 2));
                    }
                }
    }
    CP_WAIT0();       // proj weights landed (issued long ago)
    __syncthreads();

    // ---- proj gemm + epilogue to global ----
    {
        float acc[2][2][4];
        #pragma unroll
        for (int mi = 0; mi < 2; ++mi)
            #pragma unroll
            for (int ni = 0; ni < 2; ++ni)
                #pragma unroll
                for (int q = 0; q < 4; ++q) acc[mi][ni][q] = 0.f;

        hmma_gemm_128(sb + SM_XHI, sb + SM_XLO, sb + SM_WHI, sb + SM_WLO, wid, lane, acc);

        float* og = out + (size_t)bnw * NTOK * DIMC;
        const int m0 = (wid >> 3) * 32, n0 = (wid & 7) * 16;
        #pragma unroll
        for (int mi = 0; mi < 2; ++mi)
            #pragma unroll
            for (int ni = 0; ni < 2; ++ni) {
                int col = n0 + ni * 8 + tc;
                float b0 = proj_b[col], b1 = proj_b[col + 1];
                #pragma unroll
                for (int h2 = 0; h2 < 2; ++h2) {
                    int m = m0 + mi * 16 + tr + h2 * 8;
                    if (m < NTOK) {
                        og[m * DIMC + col]     = acc[mi][ni][2 * h2]     + b0;
                        og[m * DIMC + col + 1] = acc[mi][ni][2 * h2 + 1] + b1;
                    }
                }
            }
    }
}

extern "C" void kernel_launch(void* const* d_in, const int* in_sizes, int n_in,
                              void* d_out, int out_size)
{
    const float* x         = (const float*)d_in[0];
    const float* attn_mask = (const float*)d_in[1];
    const float* qkv_w     = (const float*)d_in[2];
    const float* qkv_b     = (const float*)d_in[3];
    const float* proj_w    = (const float*)d_in[4];
    const float* proj_b    = (const float*)d_in[5];
    const float* rpb_table = (const float*)d_in[6];
    const int*   rpb_index = (const int*)d_in[7];
    float*       out       = (float*)d_out;

    const int bnw = in_sizes[0] / (NTOK * DIMC);   // 8192

    prep_weights<<<(4 * 128 * 64 + 255) / 256, 256>>>(qkv_w, proj_w);
    prep_comb<<<(NWIN * NHEAD * NTOK * NTOK + 255) / 256, 256>>>(attn_mask, rpb_table, rpb_index);

    cudaFuncSetAttribute(swin_attn_kernel,
                         cudaFuncAttributeMaxDynamicSharedMemorySize, SMEM_TOTAL);

    swin_attn_kernel<<<bnw, NTHREADS, SMEM_TOTAL>>>(x, qkv_b, proj_b, out);
}

// round 11
// speedup vs baseline: 2.0972x; 2.0972x over previous
#include <cuda_runtime.h>
#include <cuda_bf16.h>
#include <cstdint>

// WindowAttention fused, R10: all gemms mma.sync bf16 split hi/lo (3 products).
// 256-thread CTAs, 2 CTAs/SM. Weight B-fragments prepacked in global (L2-resident),
// loaded via LDG.128 directly in mma layout. A-operands via smem ldmatrix.

#define NTOK  49
#define DIMC  128
#define NHEAD 4
#define HDIM  32
#define NWIN  64
#define NT    256

#define APITCH 272     // 128-col bf16 tile row pitch (17*16B)
#define VPITCH 144     // 64-col bf16 tile row pitch (9*16B)

// smem layout (bytes). XV region: X tiles, then V^T tiles, then y tiles.
#define SM_XHI 0
#define SM_XLO 18432
#define SM_VHI 0
#define SM_VLO 18432
#define SM_QHI 36864
#define SM_QLO (36864 + 17408)
#define SM_KHI (36864 + 34816)
#define SM_KLO (36864 + 52224)
#define SM_PHI SM_QHI                  // P: 196 rows * 144 * (hi,lo)
#define SM_PLO (SM_QHI + 28224)
#define SMEM_TOTAL (36864 + 69632)     // 106496 -> 2 CTAs/SM

// weight B-fragments: [chunk(4)][nb(16)][ks(8)][lane(32)] uint4 {bh0,bh1,bl0,bl1}
__device__ __align__(16) uint4 g_wfrag[4 * 16 * 8 * 32];
__device__ float g_comb[NWIN * NHEAD * NTOK * NTOK];     // bias+mask

__device__ __forceinline__ uint32_t smem_u32(const void* p) {
    uint32_t a;
    asm("{ .reg .u64 t; cvta.to.shared.u64 t, %1; cvt.u32.u64 %0, t; }" : "=r"(a) : "l"(p));
    return a;
}
__device__ __forceinline__ void ldsm4(uint32_t r[4], uint32_t a) {
    asm volatile("ldmatrix.sync.aligned.m8n8.x4.shared.b16 {%0,%1,%2,%3}, [%4];"
                 : "=r"(r[0]), "=r"(r[1]), "=r"(r[2]), "=r"(r[3]) : "r"(a));
}
__device__ __forceinline__ void ldsm2(uint32_t r[2], uint32_t a) {
    asm volatile("ldmatrix.sync.aligned.m8n8.x2.shared.b16 {%0,%1}, [%2];"
                 : "=r"(r[0]), "=r"(r[1]) : "r"(a));
}
__device__ __forceinline__ void mma16816(float c[4], const uint32_t a[4], uint32_t b0, uint32_t b1) {
    asm volatile("mma.sync.aligned.m16n8k16.row.col.f32.bf16.bf16.f32 "
                 "{%0,%1,%2,%3}, {%4,%5,%6,%7}, {%8,%9}, {%0,%1,%2,%3};"
                 : "+f"(c[0]), "+f"(c[1]), "+f"(c[2]), "+f"(c[3])
                 : "r"(a[0]), "r"(a[1]), "r"(a[2]), "r"(a[3]), "r"(b0), "r"(b1));
}
__device__ __forceinline__ void splitpair(float v0, float v1, uint32_t& hp, uint32_t& lp) {
    asm("cvt.rn.bf16x2.f32 %0, %1, %2;" : "=r"(hp) : "f"(v1), "f"(v0));
    float h0 = __uint_as_float(hp << 16);
    float h1 = __uint_as_float(hp & 0xFFFF0000u);
    asm("cvt.rn.bf16x2.f32 %0, %1, %2;" : "=r"(lp) : "f"(v1 - h1), "f"(v0 - h0));
}
__device__ __forceinline__ void split_store2(float v0, float v1, char* hi, char* lo, uint32_t off) {
    uint32_t hp, lp; splitpair(v0, v1, hp, lp);
    *(uint32_t*)(hi + off) = hp;
    *(uint32_t*)(lo + off) = lp;
}
__device__ __forceinline__ void split_store(float v, char* hi, char* lo, uint32_t off) {
    __nv_bfloat16 h = __float2bfloat16(v);
    *(__nv_bfloat16*)(hi + off) = h;
    *(__nv_bfloat16*)(lo + off) = __float2bfloat16(v - __bfloat162float(h));
}

// C[64x128] = A[64x128] * Wc^T, A from smem (APITCH tiles), B frags from L2.
// warp = (m0 = (wid>>2)*32, n-quarter nq = wid&3). acc[2][4][4].
__device__ __forceinline__ void gemm_ldg(float acc[2][4][4], int cBase /* c*16+nq*4 */,
                                         uint32_t aHi, uint32_t aLo, int lane) {
    const uint4* wf = g_wfrag + (size_t)cBase * 256 + lane;
    #pragma unroll
    for (int ks = 0; ks < 8; ++ks) {
        uint4 f[4];
        #pragma unroll
        for (int nb = 0; nb < 4; ++nb) f[nb] = wf[nb * 256 + ks * 32];
        uint32_t ah[2][4], al[2][4];
        ldsm4(ah[0], aHi + ks * 32);
        ldsm4(ah[1], aHi + 16 * APITCH + ks * 32);
        ldsm4(al[0], aLo + ks * 32);
        ldsm4(al[1], aLo + 16 * APITCH + ks * 32);
        #pragma unroll
        for (int mi = 0; mi < 2; ++mi)
            #pragma unroll
            for (int nb = 0; nb < 4; ++nb) {
                mma16816(acc[mi][nb], ah[mi], f[nb].x, f[nb].y);
                mma16816(acc[mi][nb], al[mi], f[nb].x, f[nb].y);
                mma16816(acc[mi][nb], ah[mi], f[nb].z, f[nb].w);
            }
    }
}

// ---------------- pre-kernels ----------------
__global__ void prep_wfrag(const float* __restrict__ qkv_w, const float* __restrict__ proj_w)
{
    int idx = blockIdx.x * blockDim.x + threadIdx.x;   // 16384
    if (idx >= 4 * 16 * 8 * 32) return;
    int c = idx >> 12, nb = (idx >> 8) & 15, ks = (idx >> 5) & 7, lane = idx & 31;
    int n = nb * 8 + (lane >> 2);
    int k = ks * 16 + (lane & 3) * 2;
    const float* row = (c < 3) ? (qkv_w + (size_t)(c * 128 + n) * DIMC)
                               : (proj_w + (size_t)n * DIMC);
    uint4 f;
    splitpair(row[k],     row[k + 1], f.x, f.z);
    splitpair(row[k + 8], row[k + 9], f.y, f.w);
    g_wfrag[idx] = f;
}

__global__ void prep_comb(const float* __restrict__ attn_mask,
                          const float* __restrict__ rpb_table,
                          const int*   __restrict__ rpb_index)
{
    int idx = blockIdx.x * blockDim.x + threadIdx.x;
    if (idx >= NWIN * NHEAD * NTOK * NTOK) return;
    int win = idx / (NHEAD * NTOK * NTOK);
    int rem = idx - win * (NHEAD * NTOK * NTOK);
    int h  = rem / (NTOK * NTOK);
    int ij = rem - h * (NTOK * NTOK);
    g_comb[idx] = rpb_table[rpb_index[ij] * NHEAD + h] + attn_mask[win * NTOK * NTOK + ij];
}

// ---------------- main kernel ----------------
__global__ void __launch_bounds__(NT, 2)
swin_attn_kernel(const float* __restrict__ x,
                 const float* __restrict__ qkv_b,
                 const float* __restrict__ proj_b,
                 float*       __restrict__ out)
{
    extern __shared__ char smem[];
    const uint32_t sb = smem_u32(smem);
    char* xhi = smem + SM_XHI;  char* xlo = smem + SM_XLO;
    char* vhi = smem + SM_VHI;  char* vlo = smem + SM_VLO;
    char* qhi = smem + SM_QHI;  char* qlo = smem + SM_QLO;
    char* khi = smem + SM_KHI;  char* klo = smem + SM_KLO;
    char* phi = smem + SM_PHI;  char* plo = smem + SM_PLO;

    const int t = threadIdx.x, wid = t >> 5, lane = t & 31;
    const int bnw = blockIdx.x, win = bnw & (NWIN - 1);
    const int tr = lane >> 2, tc = (lane & 3) * 2;

    // ---- stage X (49x128) split bf16 ----
    {
        const float4* xg = (const float4*)(x + (size_t)bnw * NTOK * DIMC);
        for (int idx = t; idx < NTOK * DIMC / 4; idx += NT) {
            int r = idx >> 5, c = (idx & 31) << 2;
            float4 v = xg[idx];
            uint32_t o = (uint32_t)(r * APITCH + c * 2);
            split_store2(v.x, v.y, xhi, xlo, o);
            split_store2(v.z, v.w, xhi, xlo, o + 4);
        }
    }
    __syncthreads();   // (1)

    const int m0 = (wid >> 2) * 32, nq = wid & 3;
    const uint32_t aoffX = (uint32_t)((m0 + (lane & 15)) * APITCH + (lane & 16));

    // ---- QKV chunk 0 (Q) and 1 (K) ----
    #pragma unroll
    for (int chunk = 0; chunk < 2; ++chunk) {
        float acc[2][4][4] = {};
        gemm_ldg(acc, chunk * 16 + nq * 4, sb + SM_XHI + aoffX, sb + SM_XLO + aoffX, lane);
        char* dhi = chunk ? khi : qhi;
        char* dlo = chunk ? klo : qlo;
        #pragma unroll
        for (int mi = 0; mi < 2; ++mi)
            #pragma unroll
            for (int nb = 0; nb < 4; ++nb) {
                int col = nq * 32 + nb * 8 + tc;
                float b0 = qkv_b[chunk * 128 + col], b1 = qkv_b[chunk * 128 + col + 1];
                #pragma unroll
                for (int h2 = 0; h2 < 2; ++h2) {
                    int m = m0 + mi * 16 + tr + h2 * 8;
                    if (m < NTOK)
                        split_store2(acc[mi][nb][2 * h2] + b0, acc[mi][nb][2 * h2 + 1] + b1,
                                     dhi, dlo, (uint32_t)(m * APITCH + col * 2));
                }
            }
    }

    // ---- QKV chunk 2 (V): gemm, then sync, then write V^T over X ----
    {
        float acc[2][4][4] = {};
        gemm_ldg(acc, 2 * 16 + nq * 4, sb + SM_XHI + aoffX, sb + SM_XLO + aoffX, lane);
        __syncthreads();   // (2) all X reads done
        // zero V^T token-pad cols 49..63 (uninitialized smem there could be NaN)
        for (int idx = t; idx < 128 * 2 * 15; idx += NT) {
            int d = idx / 30, rest = idx % 30;
            int half = rest / 15, k = rest % 15;
            *(uint16_t*)(smem + SM_VHI + half * 18432 + d * VPITCH + 98 + 2 * k) = 0;
        }
        #pragma unroll
        for (int mi = 0; mi < 2; ++mi)
            #pragma unroll
            for (int nb = 0; nb < 4; ++nb) {
                int col = nq * 32 + nb * 8 + tc;
                float b0 = qkv_b[256 + col], b1 = qkv_b[256 + col + 1];
                #pragma unroll
                for (int h2 = 0; h2 < 2; ++h2) {
                    int m = m0 + mi * 16 + tr + h2 * 8;
                    if (m < NTOK) {
                        split_store(acc[mi][nb][2 * h2] + b0, vhi, vlo,
                                    (uint32_t)(col * VPITCH + m * 2));
                        split_store(acc[mi][nb][2 * h2 + 1] + b1, vhi, vlo,
                                    (uint32_t)((col + 1) * VPITCH + m * 2));
                    }
                }
            }
    }

    // ---- S = Q K^T per head (K=32, n covers all 64 cols per warp) ----
    {
        const int h = wid >> 1, ms = (wid & 1) * 32;
        const uint32_t aoff = (uint32_t)((ms + (lane & 15)) * APITCH + (lane & 16) + h * 64);
        const uint32_t boff = (uint32_t)((lane & 7) * APITCH + ((lane >> 3) << 4) + h * 64);
        const uint32_t aQh = sb + SM_QHI + aoff, aQl = sb + SM_QLO + aoff;
        const uint32_t bKh = sb + SM_KHI + boff, bKl = sb + SM_KLO + boff;

        float accS[2][8][4] = {};
        #pragma unroll
        for (int half = 0; half < 2; ++half) {
            uint32_t amh[2][4], aml[2][4];
            ldsm4(amh[0], aQh + half * 32);
            ldsm4(amh[1], aQh + 16 * APITCH + half * 32);
            ldsm4(aml[0], aQl + half * 32);
            ldsm4(aml[1], aQl + 16 * APITCH + half * 32);
            #pragma unroll
            for (int nb = 0; nb < 8; ++nb) {
                uint32_t bh2[2], bl2[2];
                ldsm2(bh2, bKh + nb * 8 * APITCH + half * 32);
                ldsm2(bl2, bKl + nb * 8 * APITCH + half * 32);
                #pragma unroll
                for (int mi = 0; mi < 2; ++mi) {
                    mma16816(accS[mi][nb], amh[mi], bh2[0], bh2[1]);
                    mma16816(accS[mi][nb], aml[mi], bh2[0], bh2[1]);
                    mma16816(accS[mi][nb], amh[mi], bl2[0], bl2[1]);
                }
            }
        }
        __syncthreads();   // (3) protect Q/K from P-store clobber

        // fused softmax: each warp owns complete rows (quad shuffles only)
        const float scale = 0.17677669529663687f;
        const float* combp = g_comb + win * (NHEAD * NTOK * NTOK) + h * (NTOK * NTOK);
        #pragma unroll
        for (int mi = 0; mi < 2; ++mi)
            #pragma unroll
            for (int rh = 0; rh < 2; ++rh) {
                int i = ms + mi * 16 + tr + rh * 8;
                bool irow = (i < NTOK);
                float vr[16];
                #pragma unroll
                for (int nb = 0; nb < 8; ++nb)
                    #pragma unroll
                    for (int cc = 0; cc < 2; ++cc) {
                        int j = nb * 8 + tc + cc;
                        float a = accS[mi][nb][rh * 2 + cc];
                        vr[nb * 2 + cc] = (irow && j < NTOK)
                            ? fmaf(a, scale, combp[i * NTOK + j]) : -1e30f;
                    }
                float m = vr[0];
                #pragma unroll
                for (int q = 1; q < 16; ++q) m = fmaxf(m, vr[q]);
                m = fmaxf(m, __shfl_xor_sync(~0u, m, 1));
                m = fmaxf(m, __shfl_xor_sync(~0u, m, 2));
                float s = 0.f;
                #pragma unroll
                for (int q = 0; q < 16; ++q) { vr[q] = __expf(vr[q] - m); s += vr[q]; }
                s += __shfl_xor_sync(~0u, s, 1);
                s += __shfl_xor_sync(~0u, s, 2);
                float f = 1.f / s;
                if (irow) {
                    uint32_t prow = (uint32_t)((h * NTOK + i) * VPITCH);
                    #pragma unroll
                    for (int nb = 0; nb < 8; ++nb)
                        split_store2(vr[2 * nb] * f, vr[2 * nb + 1] * f, phi, plo,
                                     prow + (uint32_t)((nb * 8 + tc) * 2));
                }
            }
    }
    __syncthreads();   // (4) P complete

    // ---- AV: y[i][d] = P[i][:] * V^T[d][:], per head ----
    {
        const int h = wid >> 1, ms = (wid & 1) * 32;
        const uint32_t aoff = (uint32_t)((h * NTOK + ms + (lane & 15)) * VPITCH + (lane & 16));
        const uint32_t boff = (uint32_t)((h * HDIM + (lane & 7)) * VPITCH + ((lane >> 3) << 4));
        const uint32_t aPh = sb + SM_PHI + aoff, aPl = sb + SM_PLO + aoff;
        const uint32_t bVh = sb + SM_VHI + boff, bVl = sb + SM_VLO + boff;

        float accv[2][4][4] = {};
        #pragma unroll
        for (int kk = 0; kk < 4; ++kk) {
            uint32_t ah[2][4], al[2][4];
            ldsm4(ah[0], aPh + kk * 32);
            ldsm4(ah[1], aPh + 16 * VPITCH + kk * 32);
            ldsm4(al[0], aPl + kk * 32);
            ldsm4(al[1], aPl + 16 * VPITCH + kk * 32);
            #pragma unroll
            for (int nb = 0; nb < 4; ++nb) {
                uint32_t bh2[2], bl2[2];
                ldsm2(bh2, bVh + nb * 8 * VPITCH + kk * 32);
                ldsm2(bl2, bVl + nb * 8 * VPITCH + kk * 32);
                #pragma unroll
                for (int mi = 0; mi < 2; ++mi) {
                    mma16816(accv[mi][nb], ah[mi], bh2[0], bh2[1]);
                    mma16816(accv[mi][nb], al[mi], bh2[0], bh2[1]);
                    mma16816(accv[mi][nb], ah[mi], bl2[0], bl2[1]);
                }
            }
        }
        __syncthreads();   // (5) all V^T reads done before y overwrites region

        #pragma unroll
        for (int mi = 0; mi < 2; ++mi)
            #pragma unroll
            for (int nb = 0; nb < 4; ++nb)
                #pragma unroll
                for (int h2 = 0; h2 < 2; ++h2) {
                    int i = ms + mi * 16 + tr + h2 * 8;
                    if (i < NTOK) {
                        int col = h * HDIM + nb * 8 + tc;
                        split_store2(accv[mi][nb][2 * h2], accv[mi][nb][2 * h2 + 1],
                                     xhi, xlo, (uint32_t)(i * APITCH + col * 2));
                    }
                }
    }
    __syncthreads();   // (6) y complete

    // ---- proj gemm + epilogue to global ----
    {
        float acc[2][4][4] = {};
        gemm_ldg(acc, 3 * 16 + nq * 4, sb + SM_XHI + aoffX, sb + SM_XLO + aoffX, lane);

        float* og = out + (size_t)bnw * NTOK * DIMC;
        #pragma unroll
        for (int mi = 0; mi < 2; ++mi)
            #pragma unroll
            for (int nb = 0; nb < 4; ++nb) {
                int col = nq * 32 + nb * 8 + tc;
                float b0 = proj_b[col], b1 = proj_b[col + 1];
                #pragma unroll
                for (int h2 = 0; h2 < 2; ++h2) {
                    int m = m0 + mi * 16 + tr + h2 * 8;
                    if (m < NTOK) {
                        og[m * DIMC + col]     = acc[mi][nb][2 * h2]     + b0;
                        og[m * DIMC + col + 1] = acc[mi][nb][2 * h2 + 1] + b1;
                    }
                }
            }
    }
}

extern "C" void kernel_launch(void* const* d_in, const int* in_sizes, int n_in,
                              void* d_out, int out_size)
{
    const float* x         = (const float*)d_in[0];
    const float* attn_mask = (const float*)d_in[1];
    const float* qkv_w     = (const float*)d_in[2];
    const float* qkv_b     = (const float*)d_in[3];
    const float* proj_w    = (const float*)d_in[4];
    const float* proj_b    = (const float*)d_in[5];
    const float* rpb_table = (const float*)d_in[6];
    const int*   rpb_index = (const int*)d_in[7];
    float*       out       = (float*)d_out;

    const int bnw = in_sizes[0] / (NTOK * DIMC);   // 8192

    prep_wfrag<<<(4 * 16 * 8 * 32 + 255) / 256, 256>>>(qkv_w, proj_w);
    prep_comb<<<(NWIN * NHEAD * NTOK * NTOK + 255) / 256, 256>>>(attn_mask, rpb_table, rpb_index);

    cudaFuncSetAttribute(swin_attn_kernel,
                         cudaFuncAttributeMaxDynamicSharedMemorySize, SMEM_TOTAL);

    swin_attn_kernel<<<bnw, NT, SMEM_TOTAL>>>(x, qkv_b, proj_b, out);
}

// round 12
// speedup vs baseline: 2.7004x; 1.2877x over previous
#include <cuda_runtime.h>
#include <cuda_fp16.h>
#include <cstdint>

// WindowAttention fused, R11: all gemms mma.sync fp16, 2-product split
// (C = Ah*Bh + Ah*Bl; A hi-only, B split hi/lo). 256-thread CTAs, 2 CTAs/SM.
// Weight B-fragments prepacked in global (L2-resident) in mma layout.

#define NTOK  49
#define DIMC  128
#define NHEAD 4
#define HDIM  32
#define NWIN  64
#define NT    256

#define APITCH 272     // 128-col fp16 tile row pitch (17*16B)
#define VPITCH 144     // 64-col fp16 tile row pitch (9*16B)

// smem layout (bytes)
#define SM_XHI 0                     // X hi / later y hi: 64*272 = 17408
#define SM_VHI 0                     // V^T hi: 128*144 = 18432 (overlays X after V-barrier)
#define SM_VLO 18432                 // V^T lo
#define SM_QHI 36864                 // Q hi
#define SM_KHI (36864 + 17408)       // K hi
#define SM_KLO (36864 + 34816)       // K lo
#define SM_PHI SM_QHI                // P hi: 196*144 = 28224 (overlays Q/K after S)
#define SMEM_TOTAL (36864 + 52224)   // 89088 -> 2 CTAs/SM

// weight B-fragments: [chunk(4)][nb(16)][ks(8)][lane(32)] uint4 {bh0,bh1,bl0,bl1}
__device__ __align__(16) uint4 g_wfrag[4 * 16 * 8 * 32];
__device__ float g_comb[NWIN * NHEAD * NTOK * NTOK];     // bias+mask

__device__ __forceinline__ uint32_t smem_u32(const void* p) {
    uint32_t a;
    asm("{ .reg .u64 t; cvta.to.shared.u64 t, %1; cvt.u32.u64 %0, t; }" : "=r"(a) : "l"(p));
    return a;
}
__device__ __forceinline__ void ldsm4(uint32_t r[4], uint32_t a) {
    asm volatile("ldmatrix.sync.aligned.m8n8.x4.shared.b16 {%0,%1,%2,%3}, [%4];"
                 : "=r"(r[0]), "=r"(r[1]), "=r"(r[2]), "=r"(r[3]) : "r"(a));
}
__device__ __forceinline__ void ldsm2(uint32_t r[2], uint32_t a) {
    asm volatile("ldmatrix.sync.aligned.m8n8.x2.shared.b16 {%0,%1}, [%2];"
                 : "=r"(r[0]), "=r"(r[1]) : "r"(a));
}
__device__ __forceinline__ void mma16816(float c[4], const uint32_t a[4], uint32_t b0, uint32_t b1) {
    asm volatile("mma.sync.aligned.m16n8k16.row.col.f32.f16.f16.f32 "
                 "{%0,%1,%2,%3}, {%4,%5,%6,%7}, {%8,%9}, {%0,%1,%2,%3};"
                 : "+f"(c[0]), "+f"(c[1]), "+f"(c[2]), "+f"(c[3])
                 : "r"(a[0]), "r"(a[1]), "r"(a[2]), "r"(a[3]), "r"(b0), "r"(b1));
}
__device__ __forceinline__ uint32_t packh2(float v0, float v1) {
    __half2 h = __floats2half2_rn(v0, v1);
    return *(uint32_t*)&h;
}
__device__ __forceinline__ void splitpairh(float v0, float v1, uint32_t& hp, uint32_t& lp) {
    hp = packh2(v0, v1);
    __half2 h = *(__half2*)&hp;
    float2 f = __half22float2(h);
    lp = packh2(v0 - f.x, v1 - f.y);
}
__device__ __forceinline__ void store2h(float v0, float v1, char* p, uint32_t off) {
    *(uint32_t*)(p + off) = packh2(v0, v1);
}
__device__ __forceinline__ void split_store2h(float v0, float v1, char* hi, char* lo, uint32_t off) {
    uint32_t hp, lp; splitpairh(v0, v1, hp, lp);
    *(uint32_t*)(hi + off) = hp;
    *(uint32_t*)(lo + off) = lp;
}
__device__ __forceinline__ void split_storeh(float v, char* hi, char* lo, uint32_t off) {
    __half h = __float2half_rn(v);
    *(__half*)(hi + off) = h;
    *(__half*)(lo + off) = __float2half_rn(v - __half2float(h));
}

// C[64x128] = A[64x128] * Wc^T. A hi-only from smem; B frag pairs from L2.
// warp = (m0=(wid>>2)*32, nq=wid&3). acc[2][4][4]. 2 mma per (mi,nb,ks).
__device__ __forceinline__ void gemm_ldg(float acc[2][4][4], int cBase /* c*16+nq*4 */,
                                         uint32_t aHi, int lane) {
    const uint4* wf = g_wfrag + (size_t)cBase * 256 + lane;
    #pragma unroll
    for (int ks = 0; ks < 8; ++ks) {
        uint4 f[4];
        #pragma unroll
        for (int nb = 0; nb < 4; ++nb) f[nb] = wf[nb * 256 + ks * 32];
        uint32_t ah[2][4];
        ldsm4(ah[0], aHi + ks * 32);
        ldsm4(ah[1], aHi + 16 * APITCH + ks * 32);
        #pragma unroll
        for (int mi = 0; mi < 2; ++mi)
            #pragma unroll
            for (int nb = 0; nb < 4; ++nb) {
                mma16816(acc[mi][nb], ah[mi], f[nb].x, f[nb].y);
                mma16816(acc[mi][nb], ah[mi], f[nb].z, f[nb].w);
            }
    }
}

// ---------------- pre-kernels ----------------
__global__ void prep_wfrag(const float* __restrict__ qkv_w, const float* __restrict__ proj_w)
{
    int idx = blockIdx.x * blockDim.x + threadIdx.x;   // 16384
    if (idx >= 4 * 16 * 8 * 32) return;
    int c = idx >> 12, nb = (idx >> 8) & 15, ks = (idx >> 5) & 7, lane = idx & 31;
    int n = nb * 8 + (lane >> 2);
    int k = ks * 16 + (lane & 3) * 2;
    const float* row = (c < 3) ? (qkv_w + (size_t)(c * 128 + n) * DIMC)
                               : (proj_w + (size_t)n * DIMC);
    uint4 f;
    splitpairh(row[k],     row[k + 1], f.x, f.z);
    splitpairh(row[k + 8], row[k + 9], f.y, f.w);
    g_wfrag[idx] = f;
}

__global__ void prep_comb(const float* __restrict__ attn_mask,
                          const float* __restrict__ rpb_table,
                          const int*   __restrict__ rpb_index)
{
    int idx = blockIdx.x * blockDim.x + threadIdx.x;
    if (idx >= NWIN * NHEAD * NTOK * NTOK) return;
    int win = idx / (NHEAD * NTOK * NTOK);
    int rem = idx - win * (NHEAD * NTOK * NTOK);
    int h  = rem / (NTOK * NTOK);
    int ij = rem - h * (NTOK * NTOK);
    g_comb[idx] = rpb_table[rpb_index[ij] * NHEAD + h] + attn_mask[win * NTOK * NTOK + ij];
}

// ---------------- main kernel ----------------
__global__ void __launch_bounds__(NT, 2)
swin_attn_kernel(const float* __restrict__ x,
                 const float* __restrict__ qkv_b,
                 const float* __restrict__ proj_b,
                 float*       __restrict__ out)
{
    extern __shared__ char smem[];
    const uint32_t sb = smem_u32(smem);
    char* xhi = smem + SM_XHI;
    char* vhi = smem + SM_VHI;  char* vlo = smem + SM_VLO;
    char* qhi = smem + SM_QHI;
    char* khi = smem + SM_KHI;  char* klo = smem + SM_KLO;
    char* phi = smem + SM_PHI;

    const int t = threadIdx.x, wid = t >> 5, lane = t & 31;
    const int bnw = blockIdx.x, win = bnw & (NWIN - 1);
    const int tr = lane >> 2, tc = (lane & 3) * 2;

    // ---- stage X (49x128) fp16 hi ----
    {
        const float4* xg = (const float4*)(x + (size_t)bnw * NTOK * DIMC);
        for (int idx = t; idx < NTOK * DIMC / 4; idx += NT) {
            int r = idx >> 5, c = (idx & 31) << 2;
            float4 v = xg[idx];
            uint32_t o = (uint32_t)(r * APITCH + c * 2);
            store2h(v.x, v.y, xhi, o);
            store2h(v.z, v.w, xhi, o + 4);
        }
    }
    __syncthreads();   // (1)

    const int m0 = (wid >> 2) * 32, nq = wid & 3;
    const uint32_t aoffX = (uint32_t)((m0 + (lane & 15)) * APITCH + (lane & 16));

    // ---- QKV chunk 0 (Q) and 1 (K) ----
    #pragma unroll
    for (int chunk = 0; chunk < 2; ++chunk) {
        float acc[2][4][4] = {};
        gemm_ldg(acc, chunk * 16 + nq * 4, sb + SM_XHI + aoffX, lane);
        #pragma unroll
        for (int mi = 0; mi < 2; ++mi)
            #pragma unroll
            for (int nb = 0; nb < 4; ++nb) {
                int col = nq * 32 + nb * 8 + tc;
                float b0 = qkv_b[chunk * 128 + col], b1 = qkv_b[chunk * 128 + col + 1];
                #pragma unroll
                for (int h2 = 0; h2 < 2; ++h2) {
                    int m = m0 + mi * 16 + tr + h2 * 8;
                    if (m < NTOK) {
                        float v0 = acc[mi][nb][2 * h2] + b0;
                        float v1 = acc[mi][nb][2 * h2 + 1] + b1;
                        if (chunk == 0) store2h(v0, v1, qhi, (uint32_t)(m * APITCH + col * 2));
                        else            split_store2h(v0, v1, khi, klo,
                                                      (uint32_t)(m * APITCH + col * 2));
                    }
                }
            }
    }

    // ---- QKV chunk 2 (V): gemm, sync, write V^T (hi+lo) over X ----
    {
        float acc[2][4][4] = {};
        gemm_ldg(acc, 2 * 16 + nq * 4, sb + SM_XHI + aoffX, lane);
        __syncthreads();   // (2) all X reads done
        // zero V^T token cols 48..63 (hi & lo) against NaN garbage; col 48 rewritten below
        for (int idx = t; idx < 128 * 2 * 8; idx += NT) {
            int d = idx >> 4, blk = (idx >> 3) & 1, w = idx & 7;
            *(uint32_t*)(smem + SM_VHI + blk * 18432 + d * VPITCH + 96 + w * 4) = 0u;
        }
        #pragma unroll
        for (int mi = 0; mi < 2; ++mi)
            #pragma unroll
            for (int nb = 0; nb < 4; ++nb) {
                int col = nq * 32 + nb * 8 + tc;
                float b0 = qkv_b[256 + col], b1 = qkv_b[256 + col + 1];
                #pragma unroll
                for (int h2 = 0; h2 < 2; ++h2) {
                    int m = m0 + mi * 16 + tr + h2 * 8;
                    if (m < NTOK) {
                        split_storeh(acc[mi][nb][2 * h2] + b0, vhi, vlo,
                                     (uint32_t)(col * VPITCH + m * 2));
                        split_storeh(acc[mi][nb][2 * h2 + 1] + b1, vhi, vlo,
                                     (uint32_t)((col + 1) * VPITCH + m * 2));
                    }
                }
            }
    }

    // ---- S = Q K^T per head (A = Q hi; B = K hi+lo) ----
    {
        const int h = wid >> 1, ms = (wid & 1) * 32;
        const uint32_t aoff = (uint32_t)((ms + (lane & 15)) * APITCH + (lane & 16) + h * 64);
        const uint32_t boff = (uint32_t)((lane & 7) * APITCH + ((lane >> 3) << 4) + h * 64);
        const uint32_t aQh = sb + SM_QHI + aoff;
        const uint32_t bKh = sb + SM_KHI + boff, bKl = sb + SM_KLO + boff;

        float accS[2][8][4] = {};
        #pragma unroll
        for (int half = 0; half < 2; ++half) {
            uint32_t amh[2][4];
            ldsm4(amh[0], aQh + half * 32);
            ldsm4(amh[1], aQh + 16 * APITCH + half * 32);
            #pragma unroll
            for (int nb = 0; nb < 8; ++nb) {
                uint32_t bh2[2], bl2[2];
                ldsm2(bh2, bKh + nb * 8 * APITCH + half * 32);
                ldsm2(bl2, bKl + nb * 8 * APITCH + half * 32);
                #pragma unroll
                for (int mi = 0; mi < 2; ++mi) {
                    mma16816(accS[mi][nb], amh[mi], bh2[0], bh2[1]);
                    mma16816(accS[mi][nb], amh[mi], bl2[0], bl2[1]);
                }
            }
        }
        __syncthreads();   // (3) Q/K reads done before P-store clobbers

        // fused softmax: each warp owns whole rows (quad shuffles only)
        const float scale = 0.17677669529663687f;
        const float* combp = g_comb + win * (NHEAD * NTOK * NTOK) + h * (NTOK * NTOK);
        #pragma unroll
        for (int mi = 0; mi < 2; ++mi)
            #pragma unroll
            for (int rh = 0; rh < 2; ++rh) {
                int i = ms + mi * 16 + tr + rh * 8;
                bool irow = (i < NTOK);
                float vr[16];
                #pragma unroll
                for (int nb = 0; nb < 8; ++nb)
                    #pragma unroll
                    for (int cc = 0; cc < 2; ++cc) {
                        int j = nb * 8 + tc + cc;
                        float a = accS[mi][nb][rh * 2 + cc];
                        vr[nb * 2 + cc] = (irow && j < NTOK)
                            ? fmaf(a, scale, combp[i * NTOK + j]) : -1e30f;
                    }
                float m = vr[0];
                #pragma unroll
                for (int q = 1; q < 16; ++q) m = fmaxf(m, vr[q]);
                m = fmaxf(m, __shfl_xor_sync(~0u, m, 1));
                m = fmaxf(m, __shfl_xor_sync(~0u, m, 2));
                float s = 0.f;
                #pragma unroll
                for (int q = 0; q < 16; ++q) { vr[q] = __expf(vr[q] - m); s += vr[q]; }
                s += __shfl_xor_sync(~0u, s, 1);
                s += __shfl_xor_sync(~0u, s, 2);
                float f = 1.f / s;
                if (irow) {
                    uint32_t prow = (uint32_t)((h * NTOK + i) * VPITCH);
                    #pragma unroll
                    for (int nb = 0; nb < 8; ++nb)
                        store2h(vr[2 * nb] * f, vr[2 * nb + 1] * f, phi,
                                prow + (uint32_t)((nb * 8 + tc) * 2));
                }
            }
    }
    __syncthreads();   // (4) P complete

    // ---- AV: A = P hi; B = V^T hi+lo ----
    {
        const int h = wid >> 1, ms = (wid & 1) * 32;
        const uint32_t aoff = (uint32_t)((h * NTOK + ms + (lane & 15)) * VPITCH + (lane & 16));
        const uint32_t boff = (uint32_t)((h * HDIM + (lane & 7)) * VPITCH + ((lane >> 3) << 4));
        const uint32_t aPh = sb + SM_PHI + aoff;
        const uint32_t bVh = sb + SM_VHI + boff, bVl = sb + SM_VLO + boff;

        float accv[2][4][4] = {};
        #pragma unroll
        for (int kk = 0; kk < 4; ++kk) {
            uint32_t ah[2][4];
            ldsm4(ah[0], aPh + kk * 32);
            ldsm4(ah[1], aPh + 16 * VPITCH + kk * 32);
            #pragma unroll
            for (int nb = 0; nb < 4; ++nb) {
                uint32_t bh2[2], bl2[2];
                ldsm2(bh2, bVh + nb * 8 * VPITCH + kk * 32);
                ldsm2(bl2, bVl + nb * 8 * VPITCH + kk * 32);
                #pragma unroll
                for (int mi = 0; mi < 2; ++mi) {
                    mma16816(accv[mi][nb], ah[mi], bh2[0], bh2[1]);
                    mma16816(accv[mi][nb], ah[mi], bl2[0], bl2[1]);
                }
            }
        }
        __syncthreads();   // (5) V^T reads done before y overwrites region

        #pragma unroll
        for (int mi = 0; mi < 2; ++mi)
            #pragma unroll
            for (int nb = 0; nb < 4; ++nb)
                #pragma unroll
                for (int h2 = 0; h2 < 2; ++h2) {
                    int i = ms + mi * 16 + tr + h2 * 8;
                    if (i < NTOK) {
                        int col = h * HDIM + nb * 8 + tc;
                        store2h(accv[mi][nb][2 * h2], accv[mi][nb][2 * h2 + 1],
                                xhi, (uint32_t)(i * APITCH + col * 2));
                    }
                }
    }
    __syncthreads();   // (6) y complete

    // ---- proj gemm + epilogue to global ----
    {
        float acc[2][4][4] = {};
        gemm_ldg(acc, 3 * 16 + nq * 4, sb + SM_XHI + aoffX, lane);

        float* og = out + (size_t)bnw * NTOK * DIMC;
        #pragma unroll
        for (int mi = 0; mi < 2; ++mi)
            #pragma unroll
            for (int nb = 0; nb < 4; ++nb) {
                int col = nq * 32 + nb * 8 + tc;
                float b0 = proj_b[col], b1 = proj_b[col + 1];
                #pragma unroll
                for (int h2 = 0; h2 < 2; ++h2) {
                    int m = m0 + mi * 16 + tr + h2 * 8;
                    if (m < NTOK) {
                        og[m * DIMC + col]     = acc[mi][nb][2 * h2]     + b0;
                        og[m * DIMC + col + 1] = acc[mi][nb][2 * h2 + 1] + b1;
                    }
                }
            }
    }
}

extern "C" void kernel_launch(void* const* d_in, const int* in_sizes, int n_in,
                              void* d_out, int out_size)
{
    const float* x         = (const float*)d_in[0];
    const float* attn_mask = (const float*)d_in[1];
    const float* qkv_w     = (const float*)d_in[2];
    const float* qkv_b     = (const float*)d_in[3];
    const float* proj_w    = (const float*)d_in[4];
    const float* proj_b    = (const float*)d_in[5];
    const float* rpb_table = (const float*)d_in[6];
    const int*   rpb_index = (const int*)d_in[7];
    float*       out       = (float*)d_out;

    const int bnw = in_sizes[0] / (NTOK * DIMC);   // 8192

    prep_wfrag<<<(4 * 16 * 8 * 32 + 255) / 256, 256>>>(qkv_w, proj_w);
    prep_comb<<<(NWIN * NHEAD * NTOK * NTOK + 255) / 256, 256>>>(attn_mask, rpb_table, rpb_index);

    cudaFuncSetAttribute(swin_attn_kernel,
                         cudaFuncAttributeMaxDynamicSharedMemorySize, SMEM_TOTAL);

    swin_attn_kernel<<<bnw, NT, SMEM_TOTAL>>>(x, qkv_b, proj_b, out);
}

// round 16
// speedup vs baseline: 3.0550x; 1.1313x over previous
#include <cuda_runtime.h>
#include <cuda_fp16.h>
#include <cstdint>

// WindowAttention fused, R15 (=R12 + typo fix): all gemms mma.sync fp16 2-product
// split (C = Ah*Bh + Ah*Bl). Weight gemms tiled m64n16/warp so each B fragment is
// fetched from L2 exactly once per CTA. comb table in fp16. 256 thr, 2 CTAs/SM.

#define NTOK  49
#define DIMC  128
#define NHEAD 4
#define HDIM  32
#define NWIN  64
#define NT    256
#define CPAD  52

#define APITCH 272     // 128-col fp16 tile row pitch (17*16B)
#define VPITCH 144     // 64-col fp16 tile row pitch (9*16B)

// smem layout (bytes)
#define SM_XHI 0                     // X hi / later y hi: 64*272 = 17408
#define SM_VHI 0                     // V^T hi: 128*144 = 18432 (overlays X after V-barrier)
#define SM_VLO 18432                 // V^T lo
#define SM_QHI 36864                 // Q hi
#define SM_KHI (36864 + 17408)       // K hi
#define SM_KLO (36864 + 34816)       // K lo
#define SM_PHI SM_QHI                // P hi: 196*144 = 28224 (overlays Q/K after S)
#define SMEM_TOTAL (36864 + 52224)   // 89088 -> 2 CTAs/SM

// weight B-fragments: [chunk(4)][nb(16)][ks(8)][lane(32)] uint4 {bh0,bh1,bl0,bl1}
__device__ __align__(16) uint4 g_wfrag[4 * 16 * 8 * 32];
__device__ __half g_combh[NWIN * NHEAD * NTOK * CPAD];   // bias+mask, fp16, padded rows

__device__ __forceinline__ uint32_t smem_u32(const void* p) {
    uint32_t a;
    asm("{ .reg .u64 t; cvta.to.shared.u64 t, %1; cvt.u32.u64 %0, t; }" : "=r"(a) : "l"(p));
    return a;
}
__device__ __forceinline__ void ldsm4(uint32_t r[4], uint32_t a) {
    asm volatile("ldmatrix.sync.aligned.m8n8.x4.shared.b16 {%0,%1,%2,%3}, [%4];"
                 : "=r"(r[0]), "=r"(r[1]), "=r"(r[2]), "=r"(r[3]) : "r"(a));
}
__device__ __forceinline__ void ldsm2(uint32_t r[2], uint32_t a) {
    asm volatile("ldmatrix.sync.aligned.m8n8.x2.shared.b16 {%0,%1}, [%2];"
                 : "=r"(r[0]), "=r"(r[1]) : "r"(a));
}
__device__ __forceinline__ void mma16816(float c[4], const uint32_t a[4], uint32_t b0, uint32_t b1) {
    asm volatile("mma.sync.aligned.m16n8k16.row.col.f32.f16.f16.f32 "
                 "{%0,%1,%2,%3}, {%4,%5,%6,%7}, {%8,%9}, {%0,%1,%2,%3};"
                 : "+f"(c[0]), "+f"(c[1]), "+f"(c[2]), "+f"(c[3])
                 : "r"(a[0]), "r"(a[1]), "r"(a[2]), "r"(a[3]), "r"(b0), "r"(b1));
}
__device__ __forceinline__ uint32_t packh2(float v0, float v1) {
    __half2 h = __floats2half2_rn(v0, v1);
    return *(uint32_t*)&h;
}
__device__ __forceinline__ void splitpairh(float v0, float v1, uint32_t& hp, uint32_t& lp) {
    hp = packh2(v0, v1);
    __half2 h = *(__half2*)&hp;
    float2 f = __half22float2(h);
    lp = packh2(v0 - f.x, v1 - f.y);
}
__device__ __forceinline__ void store2h(float v0, float v1, char* p, uint32_t off) {
    *(uint32_t*)(p + off) = packh2(v0, v1);
}
__device__ __forceinline__ void split_store2h(float v0, float v1, char* hi, char* lo, uint32_t off) {
    uint32_t hp, lp; splitpairh(v0, v1, hp, lp);
    *(uint32_t*)(hi + off) = hp;
    *(uint32_t*)(lo + off) = lp;
}
__device__ __forceinline__ void split_storeh(float v, char* hi, char* lo, uint32_t off) {
    __half h = __float2half_rn(v);
    *(__half*)(hi + off) = h;
    *(__half*)(lo + off) = __float2half_rn(v - __half2float(h));
}

// C[64x16] per warp: A[64x128] from smem (hi only), B slice (wid*16..+15) frags from L2.
// acc[4][2][4]; each B fragment read once per CTA.
__device__ __forceinline__ void gemm_ldg(float acc[4][2][4], int chunk, int wid,
                                         uint32_t aHi, int lane) {
    const uint4* wf = g_wfrag + (size_t)(chunk * 16 + wid * 2) * 256 + lane;
    #pragma unroll
    for (int ks = 0; ks < 8; ++ks) {
        uint4 f0 = wf[ks * 32];
        uint4 f1 = wf[256 + ks * 32];
        uint32_t ah[4][4];
        #pragma unroll
        for (int mi = 0; mi < 4; ++mi)
            ldsm4(ah[mi], aHi + mi * 16 * APITCH + ks * 32);
        #pragma unroll
        for (int mi = 0; mi < 4; ++mi) {
            mma16816(acc[mi][0], ah[mi], f0.x, f0.y);
            mma16816(acc[mi][0], ah[mi], f0.z, f0.w);
            mma16816(acc[mi][1], ah[mi], f1.x, f1.y);
            mma16816(acc[mi][1], ah[mi], f1.z, f1.w);
        }
    }
}

// ---------------- pre-kernels ----------------
__global__ void prep_wfrag(const float* __restrict__ qkv_w, const float* __restrict__ proj_w)
{
    int idx = blockIdx.x * blockDim.x + threadIdx.x;   // 16384
    if (idx >= 4 * 16 * 8 * 32) return;
    int c = idx >> 12, nb = (idx >> 8) & 15, ks = (idx >> 5) & 7, lane = idx & 31;
    int n = nb * 8 + (lane >> 2);
    int k = ks * 16 + (lane & 3) * 2;
    const float* row = (c < 3) ? (qkv_w + (size_t)(c * 128 + n) * DIMC)
                               : (proj_w + (size_t)n * DIMC);
    uint4 f;
    splitpairh(row[k],     row[k + 1], f.x, f.z);
    splitpairh(row[k + 8], row[k + 9], f.y, f.w);
    g_wfrag[idx] = f;
}

__global__ void prep_comb(const float* __restrict__ attn_mask,
                          const float* __restrict__ rpb_table,
                          const int*   __restrict__ rpb_index)
{
    int idx = blockIdx.x * blockDim.x + threadIdx.x;
    if (idx >= NWIN * NHEAD * NTOK * CPAD) return;
    int j = idx % CPAD;
    int r = idx / CPAD;            // win*NHEAD*NTOK + h*NTOK + i
    int i = r % NTOK;
    int hh = r / NTOK;
    int h = hh % NHEAD;
    int win = hh / NHEAD;
    float v = 0.f;
    if (j < NTOK) {
        int ij = i * NTOK + j;
        v = rpb_table[rpb_index[ij] * NHEAD + h] + attn_mask[win * NTOK * NTOK + ij];
    }
    g_combh[idx] = __float2half_rn(v);
}

// ---------------- main kernel ----------------
__global__ void __launch_bounds__(NT, 2)
swin_attn_kernel(const float* __restrict__ x,
                 const float* __restrict__ qkv_b,
                 const float* __restrict__ proj_b,
                 float*       __restrict__ out)
{
    extern __shared__ char smem[];
    const uint32_t sb = smem_u32(smem);
    char* xhi = smem + SM_XHI;
    char* vhi = smem + SM_VHI;  char* vlo = smem + SM_VLO;
    char* qhi = smem + SM_QHI;
    char* khi = smem + SM_KHI;  char* klo = smem + SM_KLO;
    char* phi = smem + SM_PHI;

    const int t = threadIdx.x, wid = t >> 5, lane = t & 31;
    const int bnw = blockIdx.x, win = bnw & (NWIN - 1);
    const int tr = lane >> 2, tc = (lane & 3) * 2;

    // ---- stage X (49x128) fp16 hi ----
    {
        const float4* xg = (const float4*)(x + (size_t)bnw * NTOK * DIMC);
        for (int idx = t; idx < NTOK * DIMC / 4; idx += NT) {
            int r = idx >> 5, c = (idx & 31) << 2;
            float4 v = xg[idx];
            uint32_t o = (uint32_t)(r * APITCH + c * 2);
            store2h(v.x, v.y, xhi, o);
            store2h(v.z, v.w, xhi, o + 4);
        }
    }
    __syncthreads();   // (1)

    const uint32_t aoffX = (uint32_t)((lane & 15) * APITCH + (lane & 16));
    const int colw = wid * 16;

    // ---- QKV chunk 0 (Q) and 1 (K): m64n16 per warp ----
    #pragma unroll
    for (int chunk = 0; chunk < 2; ++chunk) {
        float acc[4][2][4] = {};
        gemm_ldg(acc, chunk, wid, sb + SM_XHI + aoffX, lane);
        #pragma unroll
        for (int mi = 0; mi < 4; ++mi)
            #pragma unroll
            for (int nb = 0; nb < 2; ++nb) {
                int col = colw + nb * 8 + tc;
                float b0 = qkv_b[chunk * 128 + col], b1 = qkv_b[chunk * 128 + col + 1];
                #pragma unroll
                for (int h2 = 0; h2 < 2; ++h2) {
                    int m = mi * 16 + tr + h2 * 8;
                    if (m < NTOK) {
                        float v0 = acc[mi][nb][2 * h2] + b0;
                        float v1 = acc[mi][nb][2 * h2 + 1] + b1;
                        if (chunk == 0) store2h(v0, v1, qhi, (uint32_t)(m * APITCH + col * 2));
                        else            split_store2h(v0, v1, khi, klo,
                                                      (uint32_t)(m * APITCH + col * 2));
                    }
                }
            }
    }

    // ---- QKV chunk 2 (V): gemm, sync, write V^T (hi+lo) over X ----
    {
        float acc[4][2][4] = {};
        gemm_ldg(acc, 2, wid, sb + SM_XHI + aoffX, lane);
        __syncthreads();   // (2) all X reads done
        // zero V^T token cols 48..63 (hi & lo) against NaN garbage
        for (int idx = t; idx < 128 * 2 * 8; idx += NT) {
            int d = idx >> 4, blk = (idx >> 3) & 1, w = idx & 7;
            *(uint32_t*)(smem + SM_VHI + blk * 18432 + d * VPITCH + 96 + w * 4) = 0u;
        }
        #pragma unroll
        for (int mi = 0; mi < 4; ++mi)
            #pragma unroll
            for (int nb = 0; nb < 2; ++nb) {
                int col = colw + nb * 8 + tc;
                float b0 = qkv_b[256 + col], b1 = qkv_b[256 + col + 1];
                #pragma unroll
                for (int h2 = 0; h2 < 2; ++h2) {
                    int m = mi * 16 + tr + h2 * 8;
                    if (m < NTOK) {
                        split_storeh(acc[mi][nb][2 * h2] + b0, vhi, vlo,
                                     (uint32_t)(col * VPITCH + m * 2));
                        split_storeh(acc[mi][nb][2 * h2 + 1] + b1, vhi, vlo,
                                     (uint32_t)((col + 1) * VPITCH + m * 2));
                    }
                }
            }
    }

    // ---- S = Q K^T per head (A = Q hi; B = K hi+lo) ----
    {
        const int h = wid >> 1, ms = (wid & 1) * 32;
        const uint32_t aoff = (uint32_t)((ms + (lane & 15)) * APITCH + (lane & 16) + h * 64);
        const uint32_t boff = (uint32_t)((lane & 7) * APITCH + ((lane >> 3) << 4) + h * 64);
        const uint32_t aQh = sb + SM_QHI + aoff;
        const uint32_t bKh = sb + SM_KHI + boff, bKl = sb + SM_KLO + boff;

        float accS[2][8][4] = {};
        #pragma unroll
        for (int half = 0; half < 2; ++half) {
            uint32_t amh[2][4];
            ldsm4(amh[0], aQh + half * 32);
            ldsm4(amh[1], aQh + 16 * APITCH + half * 32);
            #pragma unroll
            for (int nb = 0; nb < 8; ++nb) {
                uint32_t bh2[2], bl2[2];
                ldsm2(bh2, bKh + nb * 8 * APITCH + half * 32);
                ldsm2(bl2, bKl + nb * 8 * APITCH + half * 32);
                #pragma unroll
                for (int mi = 0; mi < 2; ++mi) {
                    mma16816(accS[mi][nb], amh[mi], bh2[0], bh2[1]);
                    mma16816(accS[mi][nb], amh[mi], bl2[0], bl2[1]);
                }
            }
        }
        __syncthreads();   // (3) Q/K reads done before P-store clobbers

        // fused softmax: each warp owns whole rows (quad shuffles only)
        const float scale = 0.17677669529663687f;
        const __half* combp = g_combh + (size_t)(win * NHEAD + h) * NTOK * CPAD;
        #pragma unroll
        for (int mi = 0; mi < 2; ++mi)
            #pragma unroll
            for (int rh = 0; rh < 2; ++rh) {
                int i = ms + mi * 16 + tr + rh * 8;
                bool irow = (i < NTOK);
                float vr[16];
                #pragma unroll
                for (int nb = 0; nb < 8; ++nb) {
                    int j = nb * 8 + tc;
                    float2 cb = make_float2(0.f, 0.f);
                    if (irow && j < NTOK)
                        cb = __half22float2(*(const __half2*)(combp + i * CPAD + j));
                    float a0 = accS[mi][nb][rh * 2];
                    float a1 = accS[mi][nb][rh * 2 + 1];
                    vr[nb * 2]     = (irow && j < NTOK)     ? fmaf(a0, scale, cb.x) : -1e30f;
                    vr[nb * 2 + 1] = (irow && j + 1 < NTOK) ? fmaf(a1, scale, cb.y) : -1e30f;
                }
                float m = vr[0];
                #pragma unroll
                for (int q = 1; q < 16; ++q) m = fmaxf(m, vr[q]);
                m = fmaxf(m, __shfl_xor_sync(~0u, m, 1));
                m = fmaxf(m, __shfl_xor_sync(~0u, m, 2));
                float s = 0.f;
                #pragma unroll
                for (int q = 0; q < 16; ++q) { vr[q] = __expf(vr[q] - m); s += vr[q]; }
                s += __shfl_xor_sync(~0u, s, 1);
                s += __shfl_xor_sync(~0u, s, 2);
                float f = 1.f / s;
                if (irow) {
                    uint32_t prow = (uint32_t)((h * NTOK + i) * VPITCH);
                    #pragma unroll
                    for (int nb = 0; nb < 8; ++nb)
                        store2h(vr[2 * nb] * f, vr[2 * nb + 1] * f, phi,
                                prow + (uint32_t)((nb * 8 + tc) * 2));
                }
            }
    }
    __syncthreads();   // (4) P complete

    // ---- AV: A = P hi; B = V^T hi+lo ----
    {
        const int h = wid >> 1, ms = (wid & 1) * 32;
        const uint32_t aoff = (uint32_t)((h * NTOK + ms + (lane & 15)) * VPITCH + (lane & 16));
        const uint32_t boff = (uint32_t)((h * HDIM + (lane & 7)) * VPITCH + ((lane >> 3) << 4));
        const uint32_t aPh = sb + SM_PHI + aoff;
        const uint32_t bVh = sb + SM_VHI + boff, bVl = sb + SM_VLO + boff;

        float accv[2][4][4] = {};
        #pragma unroll
        for (int kk = 0; kk < 4; ++kk) {
            uint32_t ah[2][4];
            ldsm4(ah[0], aPh + kk * 32);
            ldsm4(ah[1], aPh + 16 * VPITCH + kk * 32);
            #pragma unroll
            for (int nb = 0; nb < 4; ++nb) {
                uint32_t bh2[2], bl2[2];
                ldsm2(bh2, bVh + nb * 8 * VPITCH + kk * 32);
                ldsm2(bl2, bVl + nb * 8 * VPITCH + kk * 32);
                #pragma unroll
                for (int mi = 0; mi < 2; ++mi) {
                    mma16816(accv[mi][nb], ah[mi], bh2[0], bh2[1]);
                    mma16816(accv[mi][nb], ah[mi], bl2[0], bl2[1]);
                }
            }
        }
        __syncthreads();   // (5) V^T reads done before y overwrites region

        #pragma unroll
        for (int mi = 0; mi < 2; ++mi)
            #pragma unroll
            for (int nb = 0; nb < 4; ++nb)
                #pragma unroll
                for (int h2 = 0; h2 < 2; ++h2) {
                    int i = ms + mi * 16 + tr + h2 * 8;
                    if (i < NTOK) {
                        int col = h * HDIM + nb * 8 + tc;
                        store2h(accv[mi][nb][2 * h2], accv[mi][nb][2 * h2 + 1],
                                xhi, (uint32_t)(i * APITCH + col * 2));
                    }
                }
    }
    __syncthreads();   // (6) y complete

    // ---- proj gemm (m64n16) + epilogue to global ----
    {
        float acc[4][2][4] = {};
        gemm_ldg(acc, 3, wid, sb + SM_XHI + aoffX, lane);

        float* og = out + (size_t)bnw * NTOK * DIMC;
        #pragma unroll
        for (int mi = 0; mi < 4; ++mi)
            #pragma unroll
            for (int nb = 0; nb < 2; ++nb) {
                int col = colw + nb * 8 + tc;
                float b0 = proj_b[col], b1 = proj_b[col + 1];
                #pragma unroll
                for (int h2 = 0; h2 < 2; ++h2) {
                    int m = mi * 16 + tr + h2 * 8;
                    if (m < NTOK)
                        *(float2*)(og + m * DIMC + col) =
                            make_float2(acc[mi][nb][2 * h2] + b0,
                                        acc[mi][nb][2 * h2 + 1] + b1);
                }
            }
    }
}

extern "C" void kernel_launch(void* const* d_in, const int* in_sizes, int n_in,
                              void* d_out, int out_size)
{
    const float* x         = (const float*)d_in[0];
    const float* attn_mask = (const float*)d_in[1];
    const float* qkv_w     = (const float*)d_in[2];
    const float* qkv_b     = (const float*)d_in[3];
    const float* proj_w    = (const float*)d_in[4];
    const float* proj_b    = (const float*)d_in[5];
    const float* rpb_table = (const float*)d_in[6];
    const int*   rpb_index = (const int*)d_in[7];
    float*       out       = (float*)d_out;

    const int bnw = in_sizes[0] / (NTOK * DIMC);   // 8192

    prep_wfrag<<<(4 * 16 * 8 * 32 + 255) / 256, 256>>>(qkv_w, proj_w);
    prep_comb<<<(NWIN * NHEAD * NTOK * CPAD + 255) / 256, 256>>>(attn_mask, rpb_table, rpb_index);

    cudaFuncSetAttribute(swin_attn_kernel,
                         cudaFuncAttributeMaxDynamicSharedMemorySize, SMEM_TOTAL);

    swin_attn_kernel<<<bnw, NT, SMEM_TOTAL>>>(x, qkv_b, proj_b, out);
}

// round 17
// speedup vs baseline: 3.0991x; 1.0144x over previous
#include <cuda_runtime.h>
#include <cuda_fp16.h>
#include <cstdint>

// WindowAttention fused, R16: fp16 2-product mma (C = Ah*Bh + Ah*Bl), 2 CTAs/SM.
// Q+K weight gemms fused (shared A ldsm); V row-major + ldsm.trans in AV;
// paired ldsm.x4 B-loads in S/AV; warp-local P->AV sync.

#define NTOK  49
#define DIMC  128
#define NHEAD 4
#define HDIM  32
#define NWIN  64
#define NT    256
#define CPAD  52

#define APITCH 272     // 128-col fp16 tile row pitch (17*16B)
#define VPITCH 144     // 64-col fp16 tile row pitch (9*16B)

// smem layout (bytes)
#define SM_XHI 0                     // X hi / V hi / later y hi: 64*272 = 17408
#define SM_VHI 0
#define SM_VLO 17408                 // V lo: 64*272
#define SM_QHI 36864                 // Q hi
#define SM_KHI (36864 + 17408)       // K hi
#define SM_KLO (36864 + 34816)       // K lo
#define SM_PHI SM_QHI                // P hi: 196*144 = 28224 (overlays Q/K after S)
#define SMEM_TOTAL (36864 + 52224)   // 89088 -> 2 CTAs/SM

// weight B-fragments: [chunk(4)][nb(16)][ks(8)][lane(32)] uint4 {bh0,bh1,bl0,bl1}
__device__ __align__(16) uint4 g_wfrag[4 * 16 * 8 * 32];
__device__ __half g_combh[NWIN * NHEAD * NTOK * CPAD];   // bias+mask, fp16, padded rows

__device__ __forceinline__ uint32_t smem_u32(const void* p) {
    uint32_t a;
    asm("{ .reg .u64 t; cvta.to.shared.u64 t, %1; cvt.u32.u64 %0, t; }" : "=r"(a) : "l"(p));
    return a;
}
__device__ __forceinline__ void ldsm4(uint32_t r[4], uint32_t a) {
    asm volatile("ldmatrix.sync.aligned.m8n8.x4.shared.b16 {%0,%1,%2,%3}, [%4];"
                 : "=r"(r[0]), "=r"(r[1]), "=r"(r[2]), "=r"(r[3]) : "r"(a));
}
__device__ __forceinline__ void ldsm4t(uint32_t r[4], uint32_t a) {
    asm volatile("ldmatrix.sync.aligned.m8n8.x4.trans.shared.b16 {%0,%1,%2,%3}, [%4];"
                 : "=r"(r[0]), "=r"(r[1]), "=r"(r[2]), "=r"(r[3]) : "r"(a));
}
__device__ __forceinline__ void mma16816(float c[4], const uint32_t a[4], uint32_t b0, uint32_t b1) {
    asm volatile("mma.sync.aligned.m16n8k16.row.col.f32.f16.f16.f32 "
                 "{%0,%1,%2,%3}, {%4,%5,%6,%7}, {%8,%9}, {%0,%1,%2,%3};"
                 : "+f"(c[0]), "+f"(c[1]), "+f"(c[2]), "+f"(c[3])
                 : "r"(a[0]), "r"(a[1]), "r"(a[2]), "r"(a[3]), "r"(b0), "r"(b1));
}
__device__ __forceinline__ uint32_t packh2(float v0, float v1) {
    __half2 h = __floats2half2_rn(v0, v1);
    return *(uint32_t*)&h;
}
__device__ __forceinline__ void splitpairh(float v0, float v1, uint32_t& hp, uint32_t& lp) {
    hp = packh2(v0, v1);
    __half2 h = *(__half2*)&hp;
    float2 f = __half22float2(h);
    lp = packh2(v0 - f.x, v1 - f.y);
}
__device__ __forceinline__ void store2h(float v0, float v1, char* p, uint32_t off) {
    *(uint32_t*)(p + off) = packh2(v0, v1);
}
__device__ __forceinline__ void split_store2h(float v0, float v1, char* hi, char* lo, uint32_t off) {
    uint32_t hp, lp; splitpairh(v0, v1, hp, lp);
    *(uint32_t*)(hi + off) = hp;
    *(uint32_t*)(lo + off) = lp;
}

// single-chunk gemm (used for V and proj): C[64x16]/warp, A hi from smem, B from L2.
__device__ __forceinline__ void gemm_ldg(float acc[4][2][4], int chunk, int wid,
                                         uint32_t aHi, int lane) {
    const uint4* wf = g_wfrag + (size_t)(chunk * 16 + wid * 2) * 256 + lane;
    #pragma unroll
    for (int ks = 0; ks < 8; ++ks) {
        uint4 f0 = wf[ks * 32];
        uint4 f1 = wf[256 + ks * 32];
        uint32_t ah[4];
        #pragma unroll
        for (int mi = 0; mi < 4; ++mi) {
            ldsm4(ah, aHi + mi * 16 * APITCH + ks * 32);
            mma16816(acc[mi][0], ah, f0.x, f0.y);
            mma16816(acc[mi][0], ah, f0.z, f0.w);
            mma16816(acc[mi][1], ah, f1.x, f1.y);
            mma16816(acc[mi][1], ah, f1.z, f1.w);
        }
    }
}

// ---------------- pre-kernels ----------------
__global__ void prep_wfrag(const float* __restrict__ qkv_w, const float* __restrict__ proj_w)
{
    int idx = blockIdx.x * blockDim.x + threadIdx.x;   // 16384
    if (idx >= 4 * 16 * 8 * 32) return;
    int c = idx >> 12, nb = (idx >> 8) & 15, ks = (idx >> 5) & 7, lane = idx & 31;
    int n = nb * 8 + (lane >> 2);
    int k = ks * 16 + (lane & 3) * 2;
    const float* row = (c < 3) ? (qkv_w + (size_t)(c * 128 + n) * DIMC)
                               : (proj_w + (size_t)n * DIMC);
    uint4 f;
    splitpairh(row[k],     row[k + 1], f.x, f.z);
    splitpairh(row[k + 8], row[k + 9], f.y, f.w);
    g_wfrag[idx] = f;
}

__global__ void prep_comb(const float* __restrict__ attn_mask,
                          const float* __restrict__ rpb_table,
                          const int*   __restrict__ rpb_index)
{
    int idx = blockIdx.x * blockDim.x + threadIdx.x;
    if (idx >= NWIN * NHEAD * NTOK * CPAD) return;
    int j = idx % CPAD;
    int r = idx / CPAD;
    int i = r % NTOK;
    int hh = r / NTOK;
    int h = hh % NHEAD;
    int win = hh / NHEAD;
    float v = 0.f;
    if (j < NTOK) {
        int ij = i * NTOK + j;
        v = rpb_table[rpb_index[ij] * NHEAD + h] + attn_mask[win * NTOK * NTOK + ij];
    }
    g_combh[idx] = __float2half_rn(v);
}

// ---------------- main kernel ----------------
__global__ void __launch_bounds__(NT, 2)
swin_attn_kernel(const float* __restrict__ x,
                 const float* __restrict__ qkv_b,
                 const float* __restrict__ proj_b,
                 float*       __restrict__ out)
{
    extern __shared__ char smem[];
    const uint32_t sb = smem_u32(smem);
    char* xhi = smem + SM_XHI;
    char* vhi = smem + SM_VHI;  char* vlo = smem + SM_VLO;
    char* qhi = smem + SM_QHI;
    char* khi = smem + SM_KHI;  char* klo = smem + SM_KLO;
    char* phi = smem + SM_PHI;

    const int t = threadIdx.x, wid = t >> 5, lane = t & 31;
    const int bnw = blockIdx.x, win = bnw & (NWIN - 1);
    const int tr = lane >> 2, tc = (lane & 3) * 2;

    // ---- stage X (49x128) fp16 hi ----
    {
        const float4* xg = (const float4*)(x + (size_t)bnw * NTOK * DIMC);
        for (int idx = t; idx < NTOK * DIMC / 4; idx += NT) {
            int r = idx >> 5, c = (idx & 31) << 2;
            float4 v = xg[idx];
            uint32_t o = (uint32_t)(r * APITCH + c * 2);
            store2h(v.x, v.y, xhi, o);
            store2h(v.z, v.w, xhi, o + 4);
        }
    }
    __syncthreads();   // (1)

    const uint32_t aoffX = (uint32_t)((lane & 15) * APITCH + (lane & 16));
    const int colw = wid * 16;

    // ---- fused Q+K weight gemm: shared A fragments, two B chunks ----
    {
        float accQ[4][2][4] = {};
        float accK[4][2][4] = {};
        {
            const uint4* wfQ = g_wfrag + (size_t)(wid * 2) * 256 + lane;
            const uint4* wfK = wfQ + 16 * 256;
            const uint32_t aHi = sb + SM_XHI + aoffX;
            #pragma unroll
            for (int ks = 0; ks < 8; ++ks) {
                uint4 q0 = wfQ[ks * 32];
                uint4 q1 = wfQ[256 + ks * 32];
                uint4 k0 = wfK[ks * 32];
                uint4 k1 = wfK[256 + ks * 32];
                uint32_t ah[4];
                #pragma unroll
                for (int mi = 0; mi < 4; ++mi) {
                    ldsm4(ah, aHi + mi * 16 * APITCH + ks * 32);
                    mma16816(accQ[mi][0], ah, q0.x, q0.y);
                    mma16816(accQ[mi][0], ah, q0.z, q0.w);
                    mma16816(accQ[mi][1], ah, q1.x, q1.y);
                    mma16816(accQ[mi][1], ah, q1.z, q1.w);
                    mma16816(accK[mi][0], ah, k0.x, k0.y);
                    mma16816(accK[mi][0], ah, k0.z, k0.w);
                    mma16816(accK[mi][1], ah, k1.x, k1.y);
                    mma16816(accK[mi][1], ah, k1.z, k1.w);
                }
            }
        }
        #pragma unroll
        for (int mi = 0; mi < 4; ++mi)
            #pragma unroll
            for (int nb = 0; nb < 2; ++nb) {
                int col = colw + nb * 8 + tc;
                float q0 = qkv_b[col],       q1 = qkv_b[col + 1];
                float k0 = qkv_b[128 + col], k1 = qkv_b[128 + col + 1];
                #pragma unroll
                for (int h2 = 0; h2 < 2; ++h2) {
                    int m = mi * 16 + tr + h2 * 8;
                    if (m < NTOK) {
                        store2h(accQ[mi][nb][2 * h2] + q0, accQ[mi][nb][2 * h2 + 1] + q1,
                                qhi, (uint32_t)(m * APITCH + col * 2));
                        split_store2h(accK[mi][nb][2 * h2] + k0, accK[mi][nb][2 * h2 + 1] + k1,
                                      khi, klo, (uint32_t)(m * APITCH + col * 2));
                    }
                }
            }
    }

    // ---- V chunk: gemm, sync, write V (row-major, hi+lo) over X ----
    {
        float acc[4][2][4] = {};
        gemm_ldg(acc, 2, wid, sb + SM_XHI + aoffX, lane);
        __syncthreads();   // (2) all X reads done
        // zero V pad rows 49..63 (hi & lo): 2*255 uint4
        for (int idx = t; idx < 510; idx += NT) {
            int buf = (idx >= 255), k = idx - buf * 255;
            *(uint4*)(smem + SM_VHI + buf * 17408 + 49 * APITCH + k * 16) =
                make_uint4(0u, 0u, 0u, 0u);
        }
        #pragma unroll
        for (int mi = 0; mi < 4; ++mi)
            #pragma unroll
            for (int nb = 0; nb < 2; ++nb) {
                int col = colw + nb * 8 + tc;
                float b0 = qkv_b[256 + col], b1 = qkv_b[256 + col + 1];
                #pragma unroll
                for (int h2 = 0; h2 < 2; ++h2) {
                    int m = mi * 16 + tr + h2 * 8;
                    if (m < NTOK)
                        split_store2h(acc[mi][nb][2 * h2] + b0, acc[mi][nb][2 * h2 + 1] + b1,
                                      vhi, vlo, (uint32_t)(m * APITCH + col * 2));
                }
            }
    }

    const int g4 = lane >> 3;

    // ---- S = Q K^T per head (A = Q hi; B = K hi+lo, paired ldsm.x4) ----
    {
        const int h = wid >> 1, ms = (wid & 1) * 32;
        const uint32_t aoff = (uint32_t)((ms + (lane & 15)) * APITCH + (lane & 16) + h * 64);
        const uint32_t aQh = sb + SM_QHI + aoff;
        // B x4 pairing: lane-group g4 -> (nb offset g4>>1, k-byte offset (g4&1)*16)
        const uint32_t boffB = (uint32_t)((((g4 >> 1) * 8) + (lane & 7)) * APITCH
                                          + (g4 & 1) * 16 + h * 64);

        float accS[2][8][4] = {};
        #pragma unroll
        for (int half = 0; half < 2; ++half) {
            uint32_t amh[2][4];
            ldsm4(amh[0], aQh + half * 32);
            ldsm4(amh[1], aQh + 16 * APITCH + half * 32);
            #pragma unroll
            for (int p = 0; p < 4; ++p) {
                uint32_t bh4[4], bl4[4];
                ldsm4(bh4, sb + SM_KHI + boffB + p * 16 * APITCH + half * 32);
                ldsm4(bl4, sb + SM_KLO + boffB + p * 16 * APITCH + half * 32);
                #pragma unroll
                for (int mi = 0; mi < 2; ++mi) {
                    mma16816(accS[mi][2 * p],     amh[mi], bh4[0], bh4[1]);
                    mma16816(accS[mi][2 * p],     amh[mi], bl4[0], bl4[1]);
                    mma16816(accS[mi][2 * p + 1], amh[mi], bh4[2], bh4[3]);
                    mma16816(accS[mi][2 * p + 1], amh[mi], bl4[2], bl4[3]);
                }
            }
        }
        __syncthreads();   // (3) Q/K/V reads+writes settled before P-store clobbers Q/K

        // fused softmax: each warp owns whole rows (quad shuffles only)
        const float scale = 0.17677669529663687f;
        const __half* combp = g_combh + (size_t)(win * NHEAD + h) * NTOK * CPAD;
        #pragma unroll
        for (int mi = 0; mi < 2; ++mi)
            #pragma unroll
            for (int rh = 0; rh < 2; ++rh) {
                int i = ms + mi * 16 + tr + rh * 8;
                bool irow = (i < NTOK);
                float vr[16];
                #pragma unroll
                for (int nb = 0; nb < 8; ++nb) {
                    int j = nb * 8 + tc;
                    float2 cb = make_float2(0.f, 0.f);
                    if (irow && j < NTOK)
                        cb = __half22float2(*(const __half2*)(combp + i * CPAD + j));
                    float a0 = accS[mi][nb][rh * 2];
                    float a1 = accS[mi][nb][rh * 2 + 1];
                    vr[nb * 2]     = (irow && j < NTOK)     ? fmaf(a0, scale, cb.x) : -1e30f;
                    vr[nb * 2 + 1] = (irow && j + 1 < NTOK) ? fmaf(a1, scale, cb.y) : -1e30f;
                }
                float m = vr[0];
                #pragma unroll
                for (int q = 1; q < 16; ++q) m = fmaxf(m, vr[q]);
                m = fmaxf(m, __shfl_xor_sync(~0u, m, 1));
                m = fmaxf(m, __shfl_xor_sync(~0u, m, 2));
                float s = 0.f;
                #pragma unroll
                for (int q = 0; q < 16; ++q) { vr[q] = __expf(vr[q] - m); s += vr[q]; }
                s += __shfl_xor_sync(~0u, s, 1);
                s += __shfl_xor_sync(~0u, s, 2);
                float f = 1.f / s;
                if (irow) {
                    uint32_t prow = (uint32_t)((h * NTOK + i) * VPITCH);
                    #pragma unroll
                    for (int nb = 0; nb < 8; ++nb)
                        store2h(vr[2 * nb] * f, vr[2 * nb + 1] * f, phi,
                                prow + (uint32_t)((nb * 8 + tc) * 2));
                }
            }
    }
    __syncwarp();   // (4) AV's P reads are warp-local: warp-level sync suffices

    // ---- AV: A = P hi (warp-own rows); B = V rows (trans ldsm.x4, hi+lo) ----
    {
        const int h = wid >> 1, ms = (wid & 1) * 32;
        const uint32_t aoff = (uint32_t)((h * NTOK + ms + (lane & 15)) * VPITCH + (lane & 16));
        const uint32_t aPh = sb + SM_PHI + aoff;
        // trans pairing: g4&1 -> token +8 rows, g4>>1 -> dim +8 cols
        const uint32_t voffB = (uint32_t)((((g4 & 1) * 8) + (lane & 7)) * APITCH
                                          + (h * 32 + (g4 >> 1) * 8) * 2);

        float accv[2][4][4] = {};
        #pragma unroll
        for (int kk = 0; kk < 4; ++kk) {
            uint32_t ah[2][4];
            ldsm4(ah[0], aPh + kk * 32);
            ldsm4(ah[1], aPh + 16 * VPITCH + kk * 32);
            #pragma unroll
            for (int p = 0; p < 2; ++p) {
                uint32_t bh4[4], bl4[4];
                ldsm4t(bh4, sb + SM_VHI + voffB + kk * 16 * APITCH + p * 32);
                ldsm4t(bl4, sb + SM_VLO + voffB + kk * 16 * APITCH + p * 32);
                #pragma unroll
                for (int mi = 0; mi < 2; ++mi) {
                    mma16816(accv[mi][2 * p],     ah[mi], bh4[0], bh4[1]);
                    mma16816(accv[mi][2 * p],     ah[mi], bl4[0], bl4[1]);
                    mma16816(accv[mi][2 * p + 1], ah[mi], bh4[2], bh4[3]);
                    mma16816(accv[mi][2 * p + 1], ah[mi], bl4[2], bl4[3]);
                }
            }
        }
        __syncthreads();   // (5) V reads done before y overwrites region

        #pragma unroll
        for (int mi = 0; mi < 2; ++mi)
            #pragma unroll
            for (int nb = 0; nb < 4; ++nb)
                #pragma unroll
                for (int h2 = 0; h2 < 2; ++h2) {
                    int i = ms + mi * 16 + tr + h2 * 8;
                    if (i < NTOK) {
                        int col = h * HDIM + nb * 8 + tc;
                        store2h(accv[mi][nb][2 * h2], accv[mi][nb][2 * h2 + 1],
                                xhi, (uint32_t)(i * APITCH + col * 2));
                    }
                }
    }
    __syncthreads();   // (6) y complete

    // ---- proj gemm (m64n16) + epilogue to global ----
    {
        float acc[4][2][4] = {};
        gemm_ldg(acc, 3, wid, sb + SM_XHI + aoffX, lane);

        float* og = out + (size_t)bnw * NTOK * DIMC;
        #pragma unroll
        for (int mi = 0; mi < 4; ++mi)
            #pragma unroll
            for (int nb = 0; nb < 2; ++nb) {
                int col = colw + nb * 8 + tc;
                float b0 = proj_b[col], b1 = proj_b[col + 1];
                #pragma unroll
                for (int h2 = 0; h2 < 2; ++h2) {
                    int m = mi * 16 + tr + h2 * 8;
                    if (m < NTOK)
                        *(float2*)(og + m * DIMC + col) =
                            make_float2(acc[mi][nb][2 * h2] + b0,
                                        acc[mi][nb][2 * h2 + 1] + b1);
                }
            }
    }
}

extern "C" void kernel_launch(void* const* d_in, const int* in_sizes, int n_in,
                              void* d_out, int out_size)
{
    const float* x         = (const float*)d_in[0];
    const float* attn_mask = (const float*)d_in[1];
    const float* qkv_w     = (const float*)d_in[2];
    const float* qkv_b     = (const float*)d_in[3];
    const float* proj_w    = (const float*)d_in[4];
    const float* proj_b    = (const float*)d_in[5];
    const float* rpb_table = (const float*)d_in[6];
    const int*   rpb_index = (const int*)d_in[7];
    float*       out       = (float*)d_out;

    const int bnw = in_sizes[0] / (NTOK * DIMC);   // 8192

    prep_wfrag<<<(4 * 16 * 8 * 32 + 255) / 256, 256>>>(qkv_w, proj_w);
    prep_comb<<<(NWIN * NHEAD * NTOK * CPAD + 255) / 256, 256>>>(attn_mask, rpb_table, rpb_index);

    cudaFuncSetAttribute(swin_attn_kernel,
                         cudaFuncAttributeMaxDynamicSharedMemorySize, SMEM_TOTAL);

    swin_attn_kernel<<<bnw, NT, SMEM_TOTAL>>>(x, qkv_b, proj_b, out);
}